// round 1
// baseline (speedup 1.0000x reference)
#include <cuda_runtime.h>
#include <cuda_bf16.h>
#include <math.h>

// ---------------- problem constants ----------------
#define B_   2048
#define S_   5
#define N_   80
#define E_   592
#define FX_  8
#define FF_  4
#define FE_  8
#define D_   8
#define H_   800
#define NG_  (B_ * S_)            // 10240 graphs
#define XDIM_ (N_ * D_)           // 640
#define EDIM_ (E_ * D_)           // 4736
#define SEQ_  (XDIM_ + EDIM_)     // 5376
#define G3H_  (3 * H_)            // 2400
#define MLP1_ 1280
#define OUTN_ 400                 // S_*80

// ---------------- scratch (__device__ globals: allocation-free) ----------------
__device__ float g_seq[(size_t)NG_ * SEQ_];   // [10240, 5376]
__device__ float g_gi [(size_t)NG_ * G3H_];   // [10240, 2400]
__device__ float g_gh [(size_t)B_  * G3H_];   // [2048, 2400]
__device__ float g_h  [(size_t)B_  * H_];     // [2048, 800]
__device__ float g_y  [(size_t)B_  * S_ * H_];// [2048, 4000]
__device__ float g_z1 [(size_t)B_  * MLP1_];  // [2048, 1280]

// ---------------- GNN: one block per graph ----------------
__global__ void __launch_bounds__(256) gnn_kernel(
    const float* __restrict__ x, const int* __restrict__ edge_index,
    const float* __restrict__ edge_f, const float* __restrict__ edge_attr,
    const float* __restrict__ Wx, const float* __restrict__ We,
    const float* __restrict__ Wf, const float* __restrict__ Wedge,
    float* __restrict__ seq)
{
    const int g = blockIdx.x;
    const int tid = threadIdx.x;

    const float* xg  = x         + (size_t)g * N_ * FX_;
    const int*   ei  = edge_index+ (size_t)g * 2 * E_;
    const float* efg = edge_f    + (size_t)g * E_ * FF_;
    const float* eag = edge_attr + (size_t)g * E_ * FE_;

    __shared__ float sWx[FX_ * D_];
    __shared__ float sWe[FE_ * D_];
    __shared__ float sWf[FF_ * D_];
    __shared__ float sWedge[(2 * D_ + FE_) * D_];   // 24*8
    __shared__ float s_agg[N_ * D_];
    __shared__ float s_xout[N_ * D_];
    __shared__ float s_eag[E_ * FE_];
    __shared__ int   s_src[E_];
    __shared__ int   s_dst[E_];
    __shared__ int   s_min;

    if (tid < FX_ * D_) sWx[tid] = Wx[tid];
    if (tid < FE_ * D_) sWe[tid] = We[tid];
    if (tid < FF_ * D_) sWf[tid] = Wf[tid];
    if (tid < (2 * D_ + FE_) * D_) sWedge[tid] = Wedge[tid];
    for (int i = tid; i < N_ * D_; i += 256) s_agg[i] = 0.f;
    if (tid == 0) s_min = 0x7fffffff;
    __syncthreads();

    // min over edge_index[g, 0, :]
    int lmin = 0x7fffffff;
    for (int e = tid; e < E_; e += 256) lmin = min(lmin, ei[e]);
    atomicMin(&s_min, lmin);
    __syncthreads();
    const int mn = s_min;

    // Phase 1: edge messages + scatter-add to nodes
    for (int e = tid; e < E_; e += 256) {
        int sI = ei[e]       - mn;               // >= 0 always (min over this row)
        int dI = ei[E_ + e]  - mn;
        if (dI < 0) dI += N_;                    // JAX/NumPy negative-index wrap
        s_src[e] = sI;
        s_dst[e] = dI;
        float ea[FE_], ef[FF_];
#pragma unroll
        for (int k = 0; k < FE_; k++) { ea[k] = eag[e * FE_ + k]; s_eag[e * FE_ + k] = ea[k]; }
#pragma unroll
        for (int k = 0; k < FF_; k++) ef[k] = efg[e * FF_ + k];
#pragma unroll
        for (int d = 0; d < D_; d++) {
            float m = 0.f;
#pragma unroll
            for (int k = 0; k < FE_; k++) m = fmaf(ea[k], sWe[k * D_ + d], m);
#pragma unroll
            for (int k = 0; k < FF_; k++) m = fmaf(ef[k], sWf[k * D_ + d], m);
            m = fmaxf(m, 0.f);
            atomicAdd(&s_agg[dI * D_ + d], m);
        }
    }
    __syncthreads();

    // Phase 2: node update (residual)
    for (int n = tid; n < N_; n += 256) {
        float xv[FX_];
#pragma unroll
        for (int k = 0; k < FX_; k++) xv[k] = xg[n * FX_ + k];
#pragma unroll
        for (int d = 0; d < D_; d++) {
            float t = s_agg[n * D_ + d];
#pragma unroll
            for (int k = 0; k < FX_; k++) t = fmaf(xv[k], sWx[k * D_ + d], t);
            float xo = xv[d] + fmaxf(t, 0.f);
            s_xout[n * D_ + d] = xo;
            seq[(size_t)g * SEQ_ + n * D_ + d] = xo;
        }
    }
    __syncthreads();

    // Phase 3: edge update (residual)
    for (int e = tid; e < E_; e += 256) {
        const int sI = s_src[e], dI = s_dst[e];
        float feat[2 * D_ + FE_];
#pragma unroll
        for (int k = 0; k < D_; k++)  feat[k]        = s_xout[sI * D_ + k];
#pragma unroll
        for (int k = 0; k < D_; k++)  feat[D_ + k]   = s_xout[dI * D_ + k];
#pragma unroll
        for (int k = 0; k < FE_; k++) feat[2 * D_ + k] = s_eag[e * FE_ + k];
#pragma unroll
        for (int d = 0; d < D_; d++) {
            float t = 0.f;
#pragma unroll
            for (int k = 0; k < 2 * D_ + FE_; k++) t = fmaf(feat[k], sWedge[k * D_ + d], t);
            seq[(size_t)g * SEQ_ + XDIM_ + e * D_ + d] = s_eag[e * FE_ + d] + fmaxf(t, 0.f);
        }
    }
}

// ---------------- SGEMM 128x128x8, 256 threads, 8x8 micro-tile ----------------
// TN=true : C[m,n] = sum_k A[m*K+k] * Bm[n*K+k]   (A rowmajor [M,K], Bm rowmajor [Nn,K])
// TN=false: C[m,n] = sum_k A[m*K+k] * Bm[k*Nn+n]  (Bm rowmajor [K,Nn])
// Requires: M % 128 == 0, K % 8 == 0, Nn % 4 == 0 (Nn tail tiles guarded).
template <bool TN>
__global__ void __launch_bounds__(256) sgemm128(
    const float* __restrict__ A, const float* __restrict__ Bm,
    const float* __restrict__ bias, float* __restrict__ C,
    int M, int Nn, int K)
{
    __shared__ float As[8][128];
    __shared__ float Bs[8][128];

    const int tid = threadIdx.x;
    const int m0 = blockIdx.y * 128;
    const int n0 = blockIdx.x * 128;
    const int tx = tid & 15;
    const int ty = tid >> 4;

    float acc[8][8];
#pragma unroll
    for (int i = 0; i < 8; i++)
#pragma unroll
        for (int j = 0; j < 8; j++) acc[i][j] = 0.f;

    const int lr  = tid >> 1;          // 0..127
    const int lc  = (tid & 1) * 4;     // 0 or 4
    const int bnr = tid >> 5;          // 0..7  (NN k-row)
    const int bnc = (tid & 31) * 4;    // 0..124

    for (int k0 = 0; k0 < K; k0 += 8) {
        {
            const float4 v = *reinterpret_cast<const float4*>(A + (size_t)(m0 + lr) * K + k0 + lc);
            As[lc + 0][lr] = v.x; As[lc + 1][lr] = v.y;
            As[lc + 2][lr] = v.z; As[lc + 3][lr] = v.w;
        }
        if (TN) {
            float4 v = make_float4(0.f, 0.f, 0.f, 0.f);
            if (n0 + lr < Nn)
                v = *reinterpret_cast<const float4*>(Bm + (size_t)(n0 + lr) * K + k0 + lc);
            Bs[lc + 0][lr] = v.x; Bs[lc + 1][lr] = v.y;
            Bs[lc + 2][lr] = v.z; Bs[lc + 3][lr] = v.w;
        } else {
            float4 v = make_float4(0.f, 0.f, 0.f, 0.f);
            if (n0 + bnc < Nn)
                v = *reinterpret_cast<const float4*>(Bm + (size_t)(k0 + bnr) * Nn + n0 + bnc);
            *reinterpret_cast<float4*>(&Bs[bnr][bnc]) = v;
        }
        __syncthreads();
#pragma unroll
        for (int kk = 0; kk < 8; kk++) {
            float a[8], b[8];
#pragma unroll
            for (int i = 0; i < 4; i++) {
                a[i]     = As[kk][ty * 4 + i];
                a[4 + i] = As[kk][64 + ty * 4 + i];
            }
#pragma unroll
            for (int j = 0; j < 4; j++) {
                b[j]     = Bs[kk][tx * 4 + j];
                b[4 + j] = Bs[kk][64 + tx * 4 + j];
            }
#pragma unroll
            for (int i = 0; i < 8; i++)
#pragma unroll
                for (int j = 0; j < 8; j++)
                    acc[i][j] = fmaf(a[i], b[j], acc[i][j]);
        }
        __syncthreads();
    }

#pragma unroll
    for (int i = 0; i < 8; i++) {
        const int row = m0 + ((i < 4) ? (ty * 4 + i) : (64 + ty * 4 + i - 4));
#pragma unroll
        for (int j = 0; j < 8; j++) {
            const int col = n0 + ((j < 4) ? (tx * 4 + j) : (64 + tx * 4 + j - 4));
            if (col < Nn)
                C[(size_t)row * Nn + col] = acc[i][j] + (bias ? bias[col] : 0.f);
        }
    }
}

// ---------------- GRU pointwise gates ----------------
__global__ void __launch_bounds__(256) gru_gate(
    const float* __restrict__ gi_all, const float* __restrict__ gh,
    float* __restrict__ h, float* __restrict__ y, int t)
{
    const int idx = blockIdx.x * blockDim.x + threadIdx.x;
    if (idx >= B_ * H_) return;
    const int b = idx / H_;
    const int j = idx % H_;

    const float* gi  = gi_all + (size_t)(b * S_ + t) * G3H_;
    const float* ghb = gh + (size_t)b * G3H_;

    const float ir = gi[j],        iz = gi[H_ + j],  in = gi[2 * H_ + j];
    const float hr = ghb[j],       hz = ghb[H_ + j], hn = ghb[2 * H_ + j];

    const float r = 1.f / (1.f + expf(-(ir + hr)));
    const float z = 1.f / (1.f + expf(-(iz + hz)));
    const float n = tanhf(in + r * hn);

    const float hprev = h[idx];
    const float hnew = (1.f - z) * n + z * hprev;
    h[idx] = hnew;
    y[(size_t)b * (S_ * H_) + t * H_ + j] = hnew;
}

// ---------------- launch ----------------
extern "C" void kernel_launch(void* const* d_in, const int* in_sizes, int n_in,
                              void* d_out, int out_size)
{
    const float* x          = (const float*)d_in[0];
    const int*   edge_index = (const int*)  d_in[1];
    const float* edge_f     = (const float*)d_in[2];
    const float* edge_attr  = (const float*)d_in[3];
    const float* Wx         = (const float*)d_in[4];
    const float* We         = (const float*)d_in[5];
    const float* Wf         = (const float*)d_in[6];
    const float* Wedge      = (const float*)d_in[7];
    const float* w_ih       = (const float*)d_in[8];
    const float* w_hh       = (const float*)d_in[9];
    const float* b_ih       = (const float*)d_in[10];
    const float* b_hh       = (const float*)d_in[11];
    const float* mlp_w1     = (const float*)d_in[12];
    const float* mlp_b1     = (const float*)d_in[13];
    const float* mlp_w2     = (const float*)d_in[14];
    const float* mlp_b2     = (const float*)d_in[15];
    float* out = (float*)d_out;

    float *p_seq, *p_gi, *p_gh, *p_h, *p_y, *p_z1;
    cudaGetSymbolAddress((void**)&p_seq, g_seq);
    cudaGetSymbolAddress((void**)&p_gi,  g_gi);
    cudaGetSymbolAddress((void**)&p_gh,  g_gh);
    cudaGetSymbolAddress((void**)&p_h,   g_h);
    cudaGetSymbolAddress((void**)&p_y,   g_y);
    cudaGetSymbolAddress((void**)&p_z1,  g_z1);

    // 1) GNN over all B*S graphs -> seq [10240, 5376]
    gnn_kernel<<<NG_, 256>>>(x, edge_index, edge_f, edge_attr, Wx, We, Wf, Wedge, p_seq);

    // 2) Hoisted GRU input projection: gi = seq @ w_ih^T + b_ih  [10240, 2400]
    {
        dim3 grid((G3H_ + 127) / 128, NG_ / 128);
        sgemm128<true><<<grid, 256>>>(p_seq, w_ih, b_ih, p_gi, NG_, G3H_, SEQ_);
    }

    // 3) GRU recurrence
    cudaMemsetAsync(p_h, 0, sizeof(float) * B_ * H_);
    {
        dim3 gridh((G3H_ + 127) / 128, B_ / 128);
        for (int t = 0; t < S_; t++) {
            sgemm128<true><<<gridh, 256>>>(p_h, w_hh, b_hh, p_gh, B_, G3H_, H_);
            gru_gate<<<(B_ * H_ + 255) / 256, 256>>>(p_gi, p_gh, p_h, p_y, t);
        }
    }

    // 4) MLP
    {
        dim3 g1(MLP1_ / 128, B_ / 128);
        sgemm128<false><<<g1, 256>>>(p_y, mlp_w1, mlp_b1, p_z1, B_, MLP1_, S_ * H_);
        dim3 g2((OUTN_ + 127) / 128, B_ / 128);
        sgemm128<false><<<g2, 256>>>(p_z1, mlp_w2, mlp_b2, out, B_, OUTN_, MLP1_);
    }
}

// round 3
// speedup vs baseline: 2.3135x; 2.3135x over previous
#include <cuda_runtime.h>
#include <cuda_fp16.h>
#include <math.h>
#include <stdint.h>

// ---------------- problem constants ----------------
#define B_   2048
#define S_   5
#define N_   80
#define E_   592
#define FX_  8
#define FF_  4
#define FE_  8
#define D_   8
#define H_   800
#define NG_  (B_ * S_)            // 10240 graphs
#define XDIM_ (N_ * D_)           // 640
#define EDIM_ (E_ * D_)           // 4736
#define SEQ_  (XDIM_ + EDIM_)     // 5376 (= 84 * 64)
#define G3H_  (3 * H_)            // 2400
#define G3HP_ 2432                // padded to 19*128
#define HPAD_ 832                 // 800 padded to 13*64
#define YPAD_ 4032                // 4000 padded to 63*64
#define MLP1_ 1280
#define OUTN_ 400                 // S_*80

// ---------------- scratch (__device__ globals: allocation-free) ----------------
__device__ __align__(128) __half g_seq_h[(size_t)NG_ * SEQ_];
__device__ __align__(128) __half g_seq_l[(size_t)NG_ * SEQ_];
__device__ __align__(128) __half g_wih16[(size_t)G3HP_ * SEQ_];
__device__ __align__(128) __half g_whh16[(size_t)G3HP_ * HPAD_];
__device__ __align__(128) __half g_w1t16[(size_t)MLP1_ * YPAD_];
__device__ __align__(128) __half g_h16h[(size_t)B_ * HPAD_];
__device__ __align__(128) __half g_h16l[(size_t)B_ * HPAD_];
__device__ __align__(128) __half g_y16h[(size_t)B_ * YPAD_];
__device__ __align__(128) __half g_y16l[(size_t)B_ * YPAD_];
__device__ float g_gi [(size_t)NG_ * G3H_];
__device__ float g_gh [(size_t)B_  * G3H_];
__device__ float g_h  [(size_t)B_  * H_];
__device__ float g_z1 [(size_t)B_  * MLP1_];

// ---------------- helpers ----------------
__device__ __forceinline__ uint32_t smem_u32(const void* p) {
    uint32_t a;
    asm("{ .reg .u64 t; cvta.to.shared.u64 t, %1; cvt.u32.u64 %0, t; }"
        : "=r"(a) : "l"(p));
    return a;
}
#define SW128(o) ((o) ^ (((o) >> 3) & 0x70))

__device__ __forceinline__ void fp16_split(float v, __half& hi, __half& lo) {
    hi = __float2half_rn(v);
    lo = __float2half_rn(v - __half2float(hi));
}
__device__ __forceinline__ void cp16(uint32_t dst, const void* src) {
    asm volatile("cp.async.cg.shared.global [%0], [%1], 16;" :: "r"(dst), "l"(src));
}
__device__ __forceinline__ void cp_commit() {
    asm volatile("cp.async.commit_group;");
}
__device__ __forceinline__ void cp_wait1() {
    asm volatile("cp.async.wait_group 1;");
}
__device__ __forceinline__ void cp_wait0() {
    asm volatile("cp.async.wait_group 0;");
}
__device__ __forceinline__ void ldm4(uint32_t& r0, uint32_t& r1, uint32_t& r2, uint32_t& r3,
                                     uint32_t addr) {
    asm volatile("ldmatrix.sync.aligned.m8n8.x4.shared.b16 {%0,%1,%2,%3}, [%4];"
                 : "=r"(r0), "=r"(r1), "=r"(r2), "=r"(r3) : "r"(addr));
}
__device__ __forceinline__ void mma16816(float* c, const uint32_t* a, const uint32_t* b) {
    asm volatile(
        "mma.sync.aligned.m16n8k16.row.col.f32.f16.f16.f32 "
        "{%0,%1,%2,%3}, {%4,%5,%6,%7}, {%8,%9}, {%0,%1,%2,%3};"
        : "+f"(c[0]), "+f"(c[1]), "+f"(c[2]), "+f"(c[3])
        : "r"(a[0]), "r"(a[1]), "r"(a[2]), "r"(a[3]), "r"(b[0]), "r"(b[1]));
}

// ---------------- GNN: one block per graph, writes fp16 hi/lo seq ----------------
__global__ void __launch_bounds__(256) gnn_kernel(
    const float* __restrict__ x, const int* __restrict__ edge_index,
    const float* __restrict__ edge_f, const float* __restrict__ edge_attr,
    const float* __restrict__ Wx, const float* __restrict__ We,
    const float* __restrict__ Wf, const float* __restrict__ Wedge,
    __half* __restrict__ seq_h, __half* __restrict__ seq_l)
{
    const int g = blockIdx.x;
    const int tid = threadIdx.x;

    const float* xg  = x          + (size_t)g * N_ * FX_;
    const int*   ei  = edge_index + (size_t)g * 2 * E_;
    const float* efg = edge_f     + (size_t)g * E_ * FF_;
    const float* eag = edge_attr  + (size_t)g * E_ * FE_;

    __shared__ float sWx[FX_ * D_];
    __shared__ float sWe[FE_ * D_];
    __shared__ float sWf[FF_ * D_];
    __shared__ float sWedge[(2 * D_ + FE_) * D_];
    __shared__ float s_agg[N_ * D_];
    __shared__ float s_xout[N_ * D_];
    __shared__ float s_eag[E_ * FE_];
    __shared__ int   s_src[E_];
    __shared__ int   s_dst[E_];
    __shared__ int   s_min;

    if (tid < FX_ * D_) sWx[tid] = Wx[tid];
    if (tid < FE_ * D_) sWe[tid] = We[tid];
    if (tid < FF_ * D_) sWf[tid] = Wf[tid];
    if (tid < (2 * D_ + FE_) * D_) sWedge[tid] = Wedge[tid];
    for (int i = tid; i < N_ * D_; i += 256) s_agg[i] = 0.f;
    if (tid == 0) s_min = 0x7fffffff;
    __syncthreads();

    int lmin = 0x7fffffff;
    for (int e = tid; e < E_; e += 256) lmin = min(lmin, ei[e]);
    atomicMin(&s_min, lmin);
    __syncthreads();
    const int mn = s_min;

    for (int e = tid; e < E_; e += 256) {
        int sI = ei[e]      - mn;
        int dI = ei[E_ + e] - mn;
        if (dI < 0) dI += N_;     // JAX negative-index wrap
        s_src[e] = sI;
        s_dst[e] = dI;
        float ea[FE_], ef[FF_];
#pragma unroll
        for (int k = 0; k < FE_; k++) { ea[k] = eag[e * FE_ + k]; s_eag[e * FE_ + k] = ea[k]; }
#pragma unroll
        for (int k = 0; k < FF_; k++) ef[k] = efg[e * FF_ + k];
#pragma unroll
        for (int d = 0; d < D_; d++) {
            float m = 0.f;
#pragma unroll
            for (int k = 0; k < FE_; k++) m = fmaf(ea[k], sWe[k * D_ + d], m);
#pragma unroll
            for (int k = 0; k < FF_; k++) m = fmaf(ef[k], sWf[k * D_ + d], m);
            m = fmaxf(m, 0.f);
            atomicAdd(&s_agg[dI * D_ + d], m);
        }
    }
    __syncthreads();

    for (int n = tid; n < N_; n += 256) {
        float xv[FX_];
#pragma unroll
        for (int k = 0; k < FX_; k++) xv[k] = xg[n * FX_ + k];
#pragma unroll
        for (int d = 0; d < D_; d++) {
            float t = s_agg[n * D_ + d];
#pragma unroll
            for (int k = 0; k < FX_; k++) t = fmaf(xv[k], sWx[k * D_ + d], t);
            float xo = xv[d] + fmaxf(t, 0.f);
            s_xout[n * D_ + d] = xo;
            __half hi, lo; fp16_split(xo, hi, lo);
            seq_h[(size_t)g * SEQ_ + n * D_ + d] = hi;
            seq_l[(size_t)g * SEQ_ + n * D_ + d] = lo;
        }
    }
    __syncthreads();

    for (int e = tid; e < E_; e += 256) {
        const int sI = s_src[e], dI = s_dst[e];
        float feat[2 * D_ + FE_];
#pragma unroll
        for (int k = 0; k < D_; k++)  feat[k]          = s_xout[sI * D_ + k];
#pragma unroll
        for (int k = 0; k < D_; k++)  feat[D_ + k]     = s_xout[dI * D_ + k];
#pragma unroll
        for (int k = 0; k < FE_; k++) feat[2 * D_ + k] = s_eag[e * FE_ + k];
#pragma unroll
        for (int d = 0; d < D_; d++) {
            float t = 0.f;
#pragma unroll
            for (int k = 0; k < 2 * D_ + FE_; k++) t = fmaf(feat[k], sWedge[k * D_ + d], t);
            float eo = s_eag[e * FE_ + d] + fmaxf(t, 0.f);
            __half hi, lo; fp16_split(eo, hi, lo);
            seq_h[(size_t)g * SEQ_ + XDIM_ + e * D_ + d] = hi;
            seq_l[(size_t)g * SEQ_ + XDIM_ + e * D_ + d] = lo;
        }
    }
}

// ---------------- weight conversion kernels ----------------
__global__ void __launch_bounds__(256) conv_wih(const float* __restrict__ w,
                                                __half* __restrict__ o)
{
    size_t i = (size_t)blockIdx.x * 256 + threadIdx.x;
    if (i >= (size_t)G3HP_ * SEQ_) return;
    int n = (int)(i / SEQ_);
    o[i] = __float2half_rn(n < G3H_ ? w[i] : 0.f);
}
__global__ void __launch_bounds__(256) conv_whh(const float* __restrict__ w,
                                                __half* __restrict__ o)
{
    size_t i = (size_t)blockIdx.x * 256 + threadIdx.x;
    if (i >= (size_t)G3HP_ * HPAD_) return;
    int n = (int)(i / HPAD_);
    int k = (int)(i % HPAD_);
    o[i] = __float2half_rn((n < G3H_ && k < H_) ? w[(size_t)n * H_ + k] : 0.f);
}
__global__ void __launch_bounds__(256) conv_w1t(const float* __restrict__ w,
                                                __half* __restrict__ o)
{
    size_t i = (size_t)blockIdx.x * 256 + threadIdx.x;
    if (i >= (size_t)MLP1_ * YPAD_) return;
    int n = (int)(i / YPAD_);
    int k = (int)(i % YPAD_);
    o[i] = __float2half_rn(k < S_ * H_ ? w[(size_t)k * MLP1_ + n] : 0.f);
}

// ---------------- HMMA fp16x2 TN GEMM ----------------
// C[M,Nn] = (Ah+Al)[M,K] @ Bw[Nn,K]^T + bias,  fp32 out.
// K % 64 == 0, M % 128 == 0; Bw row-padded to gridDim.x*128.
// Tile 128x128x64, 2-stage cp.async pipeline, SW128 smem.
#define TSTAGE 49152          // Ah 16K + Al 16K + B 16K
#define TOFF_AH 0
#define TOFF_AL 16384
#define TOFF_B  32768
#define GSM_TOTAL (2 * TSTAGE)

__global__ void __launch_bounds__(256) gemm_f16x2(
    const __half* __restrict__ Ah, const __half* __restrict__ Al,
    const __half* __restrict__ Bw, const float* __restrict__ bias,
    float* __restrict__ C, int M, int Nn, int K)
{
    extern __shared__ char smem[];
    const uint32_t sbase = smem_u32(smem);
    const int tid = threadIdx.x;
    const int wid = tid >> 5, lid = tid & 31;
    const int m0 = blockIdx.y * 128;
    const int n0 = blockIdx.x * 128;

    const int wm = wid & 3;      // 0..3 -> 32-row slab
    const int wn = wid >> 2;     // 0..1 -> 64-col slab

    float acc[2][8][4];
#pragma unroll
    for (int i = 0; i < 2; i++)
#pragma unroll
        for (int j = 0; j < 8; j++)
#pragma unroll
            for (int q = 0; q < 4; q++) acc[i][j][q] = 0.f;

    // loader: each thread owns row = tid>>1, 16B chunks (tid&1)*4 .. +3
    const int lrow = tid >> 1;
    const int lkc0 = (tid & 1) * 4;

    const int nch = K / 64;

    auto load_stage = [&](int st, int c) {
        const int k0 = c * 64;
        const uint32_t stb = sbase + st * TSTAGE;
#pragma unroll
        for (int i = 0; i < 4; i++) {
            const int kc = lkc0 + i;
            const uint32_t so = SW128((uint32_t)(lrow * 128 + kc * 16));
            cp16(stb + TOFF_AH + so, Ah + (size_t)(m0 + lrow) * K + k0 + kc * 8);
            cp16(stb + TOFF_AL + so, Al + (size_t)(m0 + lrow) * K + k0 + kc * 8);
            cp16(stb + TOFF_B  + so, Bw + (size_t)(n0 + lrow) * K + k0 + kc * 8);
        }
        cp_commit();
    };

    load_stage(0, 0);

    const int lt = lid >> 3;   // ldmatrix tile index 0..3
    const int lr = lid & 7;    // row within tile

    for (int c = 0; c < nch; c++) {
        if (c + 1 < nch) load_stage((c + 1) & 1, c + 1);
        if (c + 1 < nch) cp_wait1(); else cp_wait0();
        __syncthreads();

        const uint32_t stb = sbase + (c & 1) * TSTAGE;
#pragma unroll
        for (int kk = 0; kk < 4; kk++) {
            const int kc = kk * 2 + (lt >> 1);
            // A fragments (hi and lo), 2 m16 tiles
            uint32_t aH[2][4], aL[2][4];
#pragma unroll
            for (int mt = 0; mt < 2; mt++) {
                const int row = wm * 32 + mt * 16 + (lt & 1) * 8 + lr;
                const uint32_t so = SW128((uint32_t)(row * 128 + kc * 16));
                ldm4(aH[mt][0], aH[mt][1], aH[mt][2], aH[mt][3], stb + TOFF_AH + so);
                ldm4(aL[mt][0], aL[mt][1], aL[mt][2], aL[mt][3], stb + TOFF_AL + so);
            }
            // B fragments: 4 x4-loads cover n64 x k16
            uint32_t bf[8][2];
#pragma unroll
            for (int nt = 0; nt < 4; nt++) {
                const int row = wn * 64 + nt * 16 + (lt & 1) * 8 + lr;
                const uint32_t so = SW128((uint32_t)(row * 128 + kc * 16));
                uint32_t q0, q1, q2, q3;
                ldm4(q0, q1, q2, q3, stb + TOFF_B + so);
                bf[nt * 2][0] = q0; bf[nt * 2][1] = q2;
                bf[nt * 2 + 1][0] = q1; bf[nt * 2 + 1][1] = q3;
            }
#pragma unroll
            for (int mt = 0; mt < 2; mt++)
#pragma unroll
                for (int ns = 0; ns < 8; ns++) {
                    mma16816(acc[mt][ns], aH[mt], bf[ns]);
                    mma16816(acc[mt][ns], aL[mt], bf[ns]);
                }
        }
        __syncthreads();
    }

    // epilogue
    const int gq = lid >> 2;   // group 0..7
    const int tq = lid & 3;
#pragma unroll
    for (int mt = 0; mt < 2; mt++) {
#pragma unroll
        for (int ns = 0; ns < 8; ns++) {
            const int col = n0 + wn * 64 + ns * 8 + tq * 2;
            const int r0 = m0 + wm * 32 + mt * 16 + gq;
            if (col < Nn) {
                C[(size_t)r0 * Nn + col]           = acc[mt][ns][0] + bias[col];
                C[(size_t)(r0 + 8) * Nn + col]     = acc[mt][ns][2] + bias[col];
            }
            if (col + 1 < Nn) {
                C[(size_t)r0 * Nn + col + 1]       = acc[mt][ns][1] + bias[col + 1];
                C[(size_t)(r0 + 8) * Nn + col + 1] = acc[mt][ns][3] + bias[col + 1];
            }
        }
    }
}

// ---------------- fp32 SGEMM 128x128x8 (MLP2 only) ----------------
__global__ void __launch_bounds__(256) sgemm128_nn(
    const float* __restrict__ A, const float* __restrict__ Bm,
    const float* __restrict__ bias, float* __restrict__ C,
    int M, int Nn, int K)
{
    __shared__ float As[8][128];
    __shared__ float Bs[8][128];

    const int tid = threadIdx.x;
    const int m0 = blockIdx.y * 128;
    const int n0 = blockIdx.x * 128;
    const int tx = tid & 15;
    const int ty = tid >> 4;

    float acc[8][8];
#pragma unroll
    for (int i = 0; i < 8; i++)
#pragma unroll
        for (int j = 0; j < 8; j++) acc[i][j] = 0.f;

    const int lr  = tid >> 1;
    const int lc  = (tid & 1) * 4;
    const int bnr = tid >> 5;
    const int bnc = (tid & 31) * 4;

    for (int k0 = 0; k0 < K; k0 += 8) {
        {
            const float4 v = *reinterpret_cast<const float4*>(A + (size_t)(m0 + lr) * K + k0 + lc);
            As[lc + 0][lr] = v.x; As[lc + 1][lr] = v.y;
            As[lc + 2][lr] = v.z; As[lc + 3][lr] = v.w;
        }
        {
            float4 v = make_float4(0.f, 0.f, 0.f, 0.f);
            if (n0 + bnc < Nn)
                v = *reinterpret_cast<const float4*>(Bm + (size_t)(k0 + bnr) * Nn + n0 + bnc);
            *reinterpret_cast<float4*>(&Bs[bnr][bnc]) = v;
        }
        __syncthreads();
#pragma unroll
        for (int kk = 0; kk < 8; kk++) {
            float a[8], b[8];
#pragma unroll
            for (int i = 0; i < 4; i++) {
                a[i]     = As[kk][ty * 4 + i];
                a[4 + i] = As[kk][64 + ty * 4 + i];
            }
#pragma unroll
            for (int j = 0; j < 4; j++) {
                b[j]     = Bs[kk][tx * 4 + j];
                b[4 + j] = Bs[kk][64 + tx * 4 + j];
            }
#pragma unroll
            for (int i = 0; i < 8; i++)
#pragma unroll
                for (int j = 0; j < 8; j++)
                    acc[i][j] = fmaf(a[i], b[j], acc[i][j]);
        }
        __syncthreads();
    }

#pragma unroll
    for (int i = 0; i < 8; i++) {
        const int row = m0 + ((i < 4) ? (ty * 4 + i) : (64 + ty * 4 + i - 4));
#pragma unroll
        for (int j = 0; j < 8; j++) {
            const int col = n0 + ((j < 4) ? (tx * 4 + j) : (64 + tx * 4 + j - 4));
            if (col < Nn)
                C[(size_t)row * Nn + col] = acc[i][j] + (bias ? bias[col] : 0.f);
        }
    }
}

// ---------------- GRU pointwise gates ----------------
__global__ void __launch_bounds__(256) gru_gate(
    const float* __restrict__ gi_all, const float* __restrict__ gh,
    float* __restrict__ h,
    __half* __restrict__ h16h, __half* __restrict__ h16l,
    __half* __restrict__ y16h, __half* __restrict__ y16l, int t)
{
    const int idx = blockIdx.x * blockDim.x + threadIdx.x;
    if (idx >= B_ * H_) return;
    const int b = idx / H_;
    const int j = idx % H_;

    const float* gi  = gi_all + (size_t)(b * S_ + t) * G3H_;
    const float* ghb = gh + (size_t)b * G3H_;

    const float ir = gi[j],  iz = gi[H_ + j],  in = gi[2 * H_ + j];
    const float hr = ghb[j], hz = ghb[H_ + j], hn = ghb[2 * H_ + j];

    const float r = 1.f / (1.f + expf(-(ir + hr)));
    const float z = 1.f / (1.f + expf(-(iz + hz)));
    const float n = tanhf(in + r * hn);

    const float hprev = h[idx];
    const float hnew = (1.f - z) * n + z * hprev;
    h[idx] = hnew;

    __half hi, lo; fp16_split(hnew, hi, lo);
    h16h[(size_t)b * HPAD_ + j] = hi;
    h16l[(size_t)b * HPAD_ + j] = lo;
    y16h[(size_t)b * YPAD_ + t * H_ + j] = hi;
    y16l[(size_t)b * YPAD_ + t * H_ + j] = lo;
}

// ---------------- launch ----------------
extern "C" void kernel_launch(void* const* d_in, const int* in_sizes, int n_in,
                              void* d_out, int out_size)
{
    const float* x          = (const float*)d_in[0];
    const int*   edge_index = (const int*)  d_in[1];
    const float* edge_f     = (const float*)d_in[2];
    const float* edge_attr  = (const float*)d_in[3];
    const float* Wx         = (const float*)d_in[4];
    const float* We         = (const float*)d_in[5];
    const float* Wf         = (const float*)d_in[6];
    const float* Wedge      = (const float*)d_in[7];
    const float* w_ih       = (const float*)d_in[8];
    const float* w_hh       = (const float*)d_in[9];
    const float* b_ih       = (const float*)d_in[10];
    const float* b_hh       = (const float*)d_in[11];
    const float* mlp_w1     = (const float*)d_in[12];
    const float* mlp_b1     = (const float*)d_in[13];
    const float* mlp_w2     = (const float*)d_in[14];
    const float* mlp_b2     = (const float*)d_in[15];
    float* out = (float*)d_out;

    __half *p_seq_h, *p_seq_l, *p_wih, *p_whh, *p_w1t, *p_h16h, *p_h16l, *p_y16h, *p_y16l;
    float *p_gi, *p_gh, *p_h, *p_z1;
    cudaGetSymbolAddress((void**)&p_seq_h, g_seq_h);
    cudaGetSymbolAddress((void**)&p_seq_l, g_seq_l);
    cudaGetSymbolAddress((void**)&p_wih,   g_wih16);
    cudaGetSymbolAddress((void**)&p_whh,   g_whh16);
    cudaGetSymbolAddress((void**)&p_w1t,   g_w1t16);
    cudaGetSymbolAddress((void**)&p_h16h,  g_h16h);
    cudaGetSymbolAddress((void**)&p_h16l,  g_h16l);
    cudaGetSymbolAddress((void**)&p_y16h,  g_y16h);
    cudaGetSymbolAddress((void**)&p_y16l,  g_y16l);
    cudaGetSymbolAddress((void**)&p_gi,    g_gi);
    cudaGetSymbolAddress((void**)&p_gh,    g_gh);
    cudaGetSymbolAddress((void**)&p_h,     g_h);
    cudaGetSymbolAddress((void**)&p_z1,    g_z1);

    static bool attr_set = false;
    if (!attr_set) {
        cudaFuncSetAttribute(gemm_f16x2, cudaFuncAttributeMaxDynamicSharedMemorySize, GSM_TOTAL);
        attr_set = true;
    }

    // 0) zero-init recurrent state + padded fp16 staging (pads must be zero)
    cudaMemsetAsync(p_h, 0, sizeof(float) * B_ * H_);
    cudaMemsetAsync(p_h16h, 0, sizeof(__half) * B_ * HPAD_);
    cudaMemsetAsync(p_h16l, 0, sizeof(__half) * B_ * HPAD_);
    cudaMemsetAsync(p_y16h, 0, sizeof(__half) * B_ * YPAD_);
    cudaMemsetAsync(p_y16l, 0, sizeof(__half) * B_ * YPAD_);

    // 1) GNN -> seq fp16 hi/lo ; weight conversions
    gnn_kernel<<<NG_, 256>>>(x, edge_index, edge_f, edge_attr, Wx, We, Wf, Wedge,
                             p_seq_h, p_seq_l);
    {
        size_t t1 = (size_t)G3HP_ * SEQ_;
        conv_wih<<<(int)((t1 + 255) / 256), 256>>>(w_ih, p_wih);
        size_t t2 = (size_t)G3HP_ * HPAD_;
        conv_whh<<<(int)((t2 + 255) / 256), 256>>>(w_hh, p_whh);
        size_t t3 = (size_t)MLP1_ * YPAD_;
        conv_w1t<<<(int)((t3 + 255) / 256), 256>>>(mlp_w1, p_w1t);
    }

    // 2) gi = seq @ w_ih^T + b_ih   [10240, 2400]  (HMMA fp16x2)
    {
        dim3 grid(G3HP_ / 128, NG_ / 128);   // 19 x 80
        gemm_f16x2<<<grid, 256, GSM_TOTAL>>>(p_seq_h, p_seq_l, p_wih, b_ih,
                                             p_gi, NG_, G3H_, SEQ_);
    }

    // 3) GRU recurrence
    {
        dim3 gridh(G3HP_ / 128, B_ / 128);   // 19 x 16
        for (int t = 0; t < S_; t++) {
            gemm_f16x2<<<gridh, 256, GSM_TOTAL>>>(p_h16h, p_h16l, p_whh, b_hh,
                                                  p_gh, B_, G3H_, HPAD_);
            gru_gate<<<(B_ * H_ + 255) / 256, 256>>>(p_gi, p_gh, p_h,
                                                     p_h16h, p_h16l, p_y16h, p_y16l, t);
        }
    }

    // 4) MLP
    {
        dim3 g1(MLP1_ / 128, B_ / 128);      // 10 x 16
        gemm_f16x2<<<g1, 256, GSM_TOTAL>>>(p_y16h, p_y16l, p_w1t, mlp_b1,
                                           p_z1, B_, MLP1_, YPAD_);
        dim3 g2((OUTN_ + 127) / 128, B_ / 128);
        sgemm128_nn<<<g2, 256>>>(p_z1, mlp_w2, mlp_b2, out, B_, OUTN_, MLP1_);
    }
}

// round 4
// speedup vs baseline: 3.0011x; 1.2972x over previous
#include <cuda_runtime.h>
#include <cuda_fp16.h>
#include <math.h>
#include <stdint.h>

// ---------------- problem constants ----------------
#define B_   2048
#define S_   5
#define N_   80
#define E_   592
#define FX_  8
#define FF_  4
#define FE_  8
#define D_   8
#define H_   800
#define NG_  (B_ * S_)            // 10240 graphs
#define XDIM_ (N_ * D_)           // 640
#define EDIM_ (E_ * D_)           // 4736
#define SEQ_  (XDIM_ + EDIM_)     // 5376 (= 84 * 64)
#define G3H_  (3 * H_)            // 2400
#define G3HP_ 2432                // padded to 19*128
#define HPAD_ 832                 // 800 padded to 13*64
#define YPAD_ 4032                // 4000 padded to 63*64
#define MLP1_ 1280
#define OUTN_ 400                 // S_*80

// ---------------- scratch (__device__ globals: allocation-free) ----------------
__device__ __align__(128) __half g_seq16[(size_t)NG_ * SEQ_];
__device__ __align__(128) __half g_wih16[(size_t)G3HP_ * SEQ_];
__device__ __align__(128) __half g_whh16[(size_t)G3HP_ * HPAD_];
__device__ __align__(128) __half g_w1t16[(size_t)MLP1_ * YPAD_];
__device__ __align__(128) __half g_h16h[(size_t)B_ * HPAD_];
__device__ __align__(128) __half g_h16l[(size_t)B_ * HPAD_];
__device__ __align__(128) __half g_y16h[(size_t)B_ * YPAD_];
__device__ __align__(128) __half g_y16l[(size_t)B_ * YPAD_];
__device__ float g_gi [(size_t)NG_ * G3H_];
__device__ float g_gh [(size_t)B_  * G3H_];
__device__ float g_h  [(size_t)B_  * H_];
__device__ float g_z1 [(size_t)B_  * MLP1_];

// ---------------- helpers ----------------
__device__ __forceinline__ uint32_t smem_u32(const void* p) {
    uint32_t a;
    asm("{ .reg .u64 t; cvta.to.shared.u64 t, %1; cvt.u32.u64 %0, t; }"
        : "=r"(a) : "l"(p));
    return a;
}
#define SW128(o) ((o) ^ (((o) >> 3) & 0x70))

__device__ __forceinline__ void fp16_split(float v, __half& hi, __half& lo) {
    hi = __float2half_rn(v);
    lo = __float2half_rn(v - __half2float(hi));
}
__device__ __forceinline__ void cp16(uint32_t dst, const void* src) {
    asm volatile("cp.async.cg.shared.global [%0], [%1], 16;" :: "r"(dst), "l"(src));
}
__device__ __forceinline__ void cp_commit() {
    asm volatile("cp.async.commit_group;");
}
__device__ __forceinline__ void cp_wait1() {
    asm volatile("cp.async.wait_group 1;");
}
__device__ __forceinline__ void cp_wait0() {
    asm volatile("cp.async.wait_group 0;");
}
__device__ __forceinline__ void ldm4(uint32_t& r0, uint32_t& r1, uint32_t& r2, uint32_t& r3,
                                     uint32_t addr) {
    asm volatile("ldmatrix.sync.aligned.m8n8.x4.shared.b16 {%0,%1,%2,%3}, [%4];"
                 : "=r"(r0), "=r"(r1), "=r"(r2), "=r"(r3) : "r"(addr));
}
__device__ __forceinline__ void mma16816(float* c, const uint32_t* a, const uint32_t* b) {
    asm volatile(
        "mma.sync.aligned.m16n8k16.row.col.f32.f16.f16.f32 "
        "{%0,%1,%2,%3}, {%4,%5,%6,%7}, {%8,%9}, {%0,%1,%2,%3};"
        : "+f"(c[0]), "+f"(c[1]), "+f"(c[2]), "+f"(c[3])
        : "r"(a[0]), "r"(a[1]), "r"(a[2]), "r"(a[3]), "r"(b[0]), "r"(b[1]));
}

// ---------------- GNN: one block per graph, writes fp16 seq ----------------
__global__ void __launch_bounds__(256) gnn_kernel(
    const float* __restrict__ x, const int* __restrict__ edge_index,
    const float* __restrict__ edge_f, const float* __restrict__ edge_attr,
    const float* __restrict__ Wx, const float* __restrict__ We,
    const float* __restrict__ Wf, const float* __restrict__ Wedge,
    __half* __restrict__ seq16)
{
    const int g = blockIdx.x;
    const int tid = threadIdx.x;

    const float* xg  = x          + (size_t)g * N_ * FX_;
    const int*   ei  = edge_index + (size_t)g * 2 * E_;
    const float* efg = edge_f     + (size_t)g * E_ * FF_;
    const float* eag = edge_attr  + (size_t)g * E_ * FE_;

    __shared__ float sWx[FX_ * D_];
    __shared__ float sWe[FE_ * D_];
    __shared__ float sWf[FF_ * D_];
    __shared__ float sWedge[(2 * D_ + FE_) * D_];
    __shared__ float s_agg[N_ * D_];
    __shared__ float s_xout[N_ * D_];
    __shared__ float s_eag[E_ * FE_];
    __shared__ int   s_src[E_];
    __shared__ int   s_dst[E_];
    __shared__ int   s_min;

    if (tid < FX_ * D_) sWx[tid] = Wx[tid];
    if (tid < FE_ * D_) sWe[tid] = We[tid];
    if (tid < FF_ * D_) sWf[tid] = Wf[tid];
    if (tid < (2 * D_ + FE_) * D_) sWedge[tid] = Wedge[tid];
    for (int i = tid; i < N_ * D_; i += 256) s_agg[i] = 0.f;
    if (tid == 0) s_min = 0x7fffffff;
    __syncthreads();

    int lmin = 0x7fffffff;
    for (int e = tid; e < E_; e += 256) lmin = min(lmin, ei[e]);
    atomicMin(&s_min, lmin);
    __syncthreads();
    const int mn = s_min;

    for (int e = tid; e < E_; e += 256) {
        int sI = ei[e]      - mn;
        int dI = ei[E_ + e] - mn;
        if (dI < 0) dI += N_;     // JAX negative-index wrap
        s_src[e] = sI;
        s_dst[e] = dI;
        float ea[FE_], ef[FF_];
#pragma unroll
        for (int k = 0; k < FE_; k++) { ea[k] = eag[e * FE_ + k]; s_eag[e * FE_ + k] = ea[k]; }
#pragma unroll
        for (int k = 0; k < FF_; k++) ef[k] = efg[e * FF_ + k];
#pragma unroll
        for (int d = 0; d < D_; d++) {
            float m = 0.f;
#pragma unroll
            for (int k = 0; k < FE_; k++) m = fmaf(ea[k], sWe[k * D_ + d], m);
#pragma unroll
            for (int k = 0; k < FF_; k++) m = fmaf(ef[k], sWf[k * D_ + d], m);
            m = fmaxf(m, 0.f);
            atomicAdd(&s_agg[dI * D_ + d], m);
        }
    }
    __syncthreads();

    for (int n = tid; n < N_; n += 256) {
        float xv[FX_];
#pragma unroll
        for (int k = 0; k < FX_; k++) xv[k] = xg[n * FX_ + k];
#pragma unroll
        for (int d = 0; d < D_; d++) {
            float t = s_agg[n * D_ + d];
#pragma unroll
            for (int k = 0; k < FX_; k++) t = fmaf(xv[k], sWx[k * D_ + d], t);
            float xo = xv[d] + fmaxf(t, 0.f);
            s_xout[n * D_ + d] = xo;
            seq16[(size_t)g * SEQ_ + n * D_ + d] = __float2half_rn(xo);
        }
    }
    __syncthreads();

    for (int e = tid; e < E_; e += 256) {
        const int sI = s_src[e], dI = s_dst[e];
        float feat[2 * D_ + FE_];
#pragma unroll
        for (int k = 0; k < D_; k++)  feat[k]          = s_xout[sI * D_ + k];
#pragma unroll
        for (int k = 0; k < D_; k++)  feat[D_ + k]     = s_xout[dI * D_ + k];
#pragma unroll
        for (int k = 0; k < FE_; k++) feat[2 * D_ + k] = s_eag[e * FE_ + k];
#pragma unroll
        for (int d = 0; d < D_; d++) {
            float t = 0.f;
#pragma unroll
            for (int k = 0; k < 2 * D_ + FE_; k++) t = fmaf(feat[k], sWedge[k * D_ + d], t);
            float eo = s_eag[e * FE_ + d] + fmaxf(t, 0.f);
            seq16[(size_t)g * SEQ_ + XDIM_ + e * D_ + d] = __float2half_rn(eo);
        }
    }
}

// ---------------- weight conversion kernels ----------------
__global__ void __launch_bounds__(256) conv_wih(const float* __restrict__ w,
                                                __half* __restrict__ o)
{
    size_t i = (size_t)blockIdx.x * 256 + threadIdx.x;
    if (i >= (size_t)G3HP_ * SEQ_) return;
    int n = (int)(i / SEQ_);
    o[i] = __float2half_rn(n < G3H_ ? w[i] : 0.f);
}
__global__ void __launch_bounds__(256) conv_whh(const float* __restrict__ w,
                                                __half* __restrict__ o)
{
    size_t i = (size_t)blockIdx.x * 256 + threadIdx.x;
    if (i >= (size_t)G3HP_ * HPAD_) return;
    int n = (int)(i / HPAD_);
    int k = (int)(i % HPAD_);
    o[i] = __float2half_rn((n < G3H_ && k < H_) ? w[(size_t)n * H_ + k] : 0.f);
}
__global__ void __launch_bounds__(256) conv_w1t(const float* __restrict__ w,
                                                __half* __restrict__ o)
{
    size_t i = (size_t)blockIdx.x * 256 + threadIdx.x;
    if (i >= (size_t)MLP1_ * YPAD_) return;
    int n = (int)(i / YPAD_);
    int k = (int)(i % YPAD_);
    o[i] = __float2half_rn(k < S_ * H_ ? w[(size_t)k * MLP1_ + n] : 0.f);
}

// ---------------- HMMA TN GEMM (templated 1-pass / 2-pass) ----------------
// PASSES==2: C = (Ah+Al) @ Bw^T + bias ; PASSES==1: C = Ah @ Bw^T + bias.
// K % 64 == 0, M % 128 == 0; Bw row-padded to gridDim.x*128.
// Tile 128x128x64, 2-stage cp.async pipeline, SW128 smem.
template <int PASSES>
__global__ void __launch_bounds__(256) gemm_f16(
    const __half* __restrict__ Ah, const __half* __restrict__ Al,
    const __half* __restrict__ Bw, const float* __restrict__ bias,
    float* __restrict__ C, int M, int Nn, int K)
{
    constexpr int TOFF_AL = 16384;
    constexpr int TOFF_B  = (PASSES == 2) ? 32768 : 16384;
    constexpr int TSTAGE  = (PASSES == 2) ? 49152 : 32768;

    extern __shared__ char smem[];
    const uint32_t sbase = smem_u32(smem);
    const int tid = threadIdx.x;
    const int wid = tid >> 5, lid = tid & 31;
    const int m0 = blockIdx.y * 128;
    const int n0 = blockIdx.x * 128;

    const int wm = wid & 3;      // 0..3 -> 32-row slab
    const int wn = wid >> 2;     // 0..1 -> 64-col slab

    float acc[2][8][4];
#pragma unroll
    for (int i = 0; i < 2; i++)
#pragma unroll
        for (int j = 0; j < 8; j++)
#pragma unroll
            for (int q = 0; q < 4; q++) acc[i][j][q] = 0.f;

    const int lrow = tid >> 1;
    const int lkc0 = (tid & 1) * 4;

    const int nch = K / 64;

    auto load_stage = [&](int st, int c) {
        const int k0 = c * 64;
        const uint32_t stb = sbase + st * TSTAGE;
#pragma unroll
        for (int i = 0; i < 4; i++) {
            const int kc = lkc0 + i;
            const uint32_t so = SW128((uint32_t)(lrow * 128 + kc * 16));
            cp16(stb + so, Ah + (size_t)(m0 + lrow) * K + k0 + kc * 8);
            if (PASSES == 2)
                cp16(stb + TOFF_AL + so, Al + (size_t)(m0 + lrow) * K + k0 + kc * 8);
            cp16(stb + TOFF_B + so, Bw + (size_t)(n0 + lrow) * K + k0 + kc * 8);
        }
        cp_commit();
    };

    load_stage(0, 0);

    const int lt = lid >> 3;   // ldmatrix tile index 0..3
    const int lr = lid & 7;    // row within tile

    for (int c = 0; c < nch; c++) {
        if (c + 1 < nch) load_stage((c + 1) & 1, c + 1);
        if (c + 1 < nch) cp_wait1(); else cp_wait0();
        __syncthreads();

        const uint32_t stb = sbase + (c & 1) * TSTAGE;
#pragma unroll
        for (int kk = 0; kk < 4; kk++) {
            const int kc = kk * 2 + (lt >> 1);
            uint32_t aH[2][4], aL[2][4];
#pragma unroll
            for (int mt = 0; mt < 2; mt++) {
                const int row = wm * 32 + mt * 16 + (lt & 1) * 8 + lr;
                const uint32_t so = SW128((uint32_t)(row * 128 + kc * 16));
                ldm4(aH[mt][0], aH[mt][1], aH[mt][2], aH[mt][3], stb + so);
                if (PASSES == 2)
                    ldm4(aL[mt][0], aL[mt][1], aL[mt][2], aL[mt][3], stb + TOFF_AL + so);
            }
            uint32_t bf[8][2];
#pragma unroll
            for (int nt = 0; nt < 4; nt++) {
                const int row = wn * 64 + nt * 16 + (lt & 1) * 8 + lr;
                const uint32_t so = SW128((uint32_t)(row * 128 + kc * 16));
                uint32_t q0, q1, q2, q3;
                ldm4(q0, q1, q2, q3, stb + TOFF_B + so);
                bf[nt * 2][0] = q0; bf[nt * 2][1] = q2;
                bf[nt * 2 + 1][0] = q1; bf[nt * 2 + 1][1] = q3;
            }
#pragma unroll
            for (int mt = 0; mt < 2; mt++)
#pragma unroll
                for (int ns = 0; ns < 8; ns++) {
                    mma16816(acc[mt][ns], aH[mt], bf[ns]);
                    if (PASSES == 2)
                        mma16816(acc[mt][ns], aL[mt], bf[ns]);
                }
        }
        __syncthreads();
    }

    // epilogue
    const int gq = lid >> 2;
    const int tq = lid & 3;
#pragma unroll
    for (int mt = 0; mt < 2; mt++) {
#pragma unroll
        for (int ns = 0; ns < 8; ns++) {
            const int col = n0 + wn * 64 + ns * 8 + tq * 2;
            const int r0 = m0 + wm * 32 + mt * 16 + gq;
            if (col < Nn) {
                C[(size_t)r0 * Nn + col]           = acc[mt][ns][0] + bias[col];
                C[(size_t)(r0 + 8) * Nn + col]     = acc[mt][ns][2] + bias[col];
            }
            if (col + 1 < Nn) {
                C[(size_t)r0 * Nn + col + 1]       = acc[mt][ns][1] + bias[col + 1];
                C[(size_t)(r0 + 8) * Nn + col + 1] = acc[mt][ns][3] + bias[col + 1];
            }
        }
    }
}

// ---------------- fp32 SGEMM 128x128x8 (MLP2 only) ----------------
__global__ void __launch_bounds__(256) sgemm128_nn(
    const float* __restrict__ A, const float* __restrict__ Bm,
    const float* __restrict__ bias, float* __restrict__ C,
    int M, int Nn, int K)
{
    __shared__ float As[8][128];
    __shared__ float Bs[8][128];

    const int tid = threadIdx.x;
    const int m0 = blockIdx.y * 128;
    const int n0 = blockIdx.x * 128;
    const int tx = tid & 15;
    const int ty = tid >> 4;

    float acc[8][8];
#pragma unroll
    for (int i = 0; i < 8; i++)
#pragma unroll
        for (int j = 0; j < 8; j++) acc[i][j] = 0.f;

    const int lr  = tid >> 1;
    const int lc  = (tid & 1) * 4;
    const int bnr = tid >> 5;
    const int bnc = (tid & 31) * 4;

    for (int k0 = 0; k0 < K; k0 += 8) {
        {
            const float4 v = *reinterpret_cast<const float4*>(A + (size_t)(m0 + lr) * K + k0 + lc);
            As[lc + 0][lr] = v.x; As[lc + 1][lr] = v.y;
            As[lc + 2][lr] = v.z; As[lc + 3][lr] = v.w;
        }
        {
            float4 v = make_float4(0.f, 0.f, 0.f, 0.f);
            if (n0 + bnc < Nn)
                v = *reinterpret_cast<const float4*>(Bm + (size_t)(k0 + bnr) * Nn + n0 + bnc);
            *reinterpret_cast<float4*>(&Bs[bnr][bnc]) = v;
        }
        __syncthreads();
#pragma unroll
        for (int kk = 0; kk < 8; kk++) {
            float a[8], b[8];
#pragma unroll
            for (int i = 0; i < 4; i++) {
                a[i]     = As[kk][ty * 4 + i];
                a[4 + i] = As[kk][64 + ty * 4 + i];
            }
#pragma unroll
            for (int j = 0; j < 4; j++) {
                b[j]     = Bs[kk][tx * 4 + j];
                b[4 + j] = Bs[kk][64 + tx * 4 + j];
            }
#pragma unroll
            for (int i = 0; i < 8; i++)
#pragma unroll
                for (int j = 0; j < 8; j++)
                    acc[i][j] = fmaf(a[i], b[j], acc[i][j]);
        }
        __syncthreads();
    }

#pragma unroll
    for (int i = 0; i < 8; i++) {
        const int row = m0 + ((i < 4) ? (ty * 4 + i) : (64 + ty * 4 + i - 4));
#pragma unroll
        for (int j = 0; j < 8; j++) {
            const int col = n0 + ((j < 4) ? (tx * 4 + j) : (64 + tx * 4 + j - 4));
            if (col < Nn)
                C[(size_t)row * Nn + col] = acc[i][j] + (bias ? bias[col] : 0.f);
        }
    }
}

// ---------------- GRU pointwise gates ----------------
__global__ void __launch_bounds__(256) gru_gate(
    const float* __restrict__ gi_all, const float* __restrict__ gh,
    float* __restrict__ h,
    __half* __restrict__ h16h, __half* __restrict__ h16l,
    __half* __restrict__ y16h, __half* __restrict__ y16l, int t)
{
    const int idx = blockIdx.x * blockDim.x + threadIdx.x;
    if (idx >= B_ * H_) return;
    const int b = idx / H_;
    const int j = idx % H_;

    const float* gi  = gi_all + (size_t)(b * S_ + t) * G3H_;
    const float* ghb = gh + (size_t)b * G3H_;

    const float ir = gi[j],  iz = gi[H_ + j],  in = gi[2 * H_ + j];
    const float hr = ghb[j], hz = ghb[H_ + j], hn = ghb[2 * H_ + j];

    const float r = 1.f / (1.f + expf(-(ir + hr)));
    const float z = 1.f / (1.f + expf(-(iz + hz)));
    const float n = tanhf(in + r * hn);

    const float hprev = h[idx];
    const float hnew = (1.f - z) * n + z * hprev;
    h[idx] = hnew;

    __half hi, lo; fp16_split(hnew, hi, lo);
    h16h[(size_t)b * HPAD_ + j] = hi;
    h16l[(size_t)b * HPAD_ + j] = lo;
    y16h[(size_t)b * YPAD_ + t * H_ + j] = hi;
    y16l[(size_t)b * YPAD_ + t * H_ + j] = lo;
}

// ---------------- launch ----------------
extern "C" void kernel_launch(void* const* d_in, const int* in_sizes, int n_in,
                              void* d_out, int out_size)
{
    const float* x          = (const float*)d_in[0];
    const int*   edge_index = (const int*)  d_in[1];
    const float* edge_f     = (const float*)d_in[2];
    const float* edge_attr  = (const float*)d_in[3];
    const float* Wx         = (const float*)d_in[4];
    const float* We         = (const float*)d_in[5];
    const float* Wf         = (const float*)d_in[6];
    const float* Wedge      = (const float*)d_in[7];
    const float* w_ih       = (const float*)d_in[8];
    const float* w_hh       = (const float*)d_in[9];
    const float* b_ih       = (const float*)d_in[10];
    const float* b_hh       = (const float*)d_in[11];
    const float* mlp_w1     = (const float*)d_in[12];
    const float* mlp_b1     = (const float*)d_in[13];
    const float* mlp_w2     = (const float*)d_in[14];
    const float* mlp_b2     = (const float*)d_in[15];
    float* out = (float*)d_out;

    __half *p_seq, *p_wih, *p_whh, *p_w1t, *p_h16h, *p_h16l, *p_y16h, *p_y16l;
    float *p_gi, *p_gh, *p_h, *p_z1;
    cudaGetSymbolAddress((void**)&p_seq,  g_seq16);
    cudaGetSymbolAddress((void**)&p_wih,  g_wih16);
    cudaGetSymbolAddress((void**)&p_whh,  g_whh16);
    cudaGetSymbolAddress((void**)&p_w1t,  g_w1t16);
    cudaGetSymbolAddress((void**)&p_h16h, g_h16h);
    cudaGetSymbolAddress((void**)&p_h16l, g_h16l);
    cudaGetSymbolAddress((void**)&p_y16h, g_y16h);
    cudaGetSymbolAddress((void**)&p_y16l, g_y16l);
    cudaGetSymbolAddress((void**)&p_gi,   g_gi);
    cudaGetSymbolAddress((void**)&p_gh,   g_gh);
    cudaGetSymbolAddress((void**)&p_h,    g_h);
    cudaGetSymbolAddress((void**)&p_z1,   g_z1);

    cudaFuncSetAttribute(gemm_f16<1>, cudaFuncAttributeMaxDynamicSharedMemorySize, 2 * 32768);
    cudaFuncSetAttribute(gemm_f16<2>, cudaFuncAttributeMaxDynamicSharedMemorySize, 2 * 49152);

    // 0) zero-init recurrent state + padded fp16 staging (pads must be zero)
    cudaMemsetAsync(p_h, 0, sizeof(float) * B_ * H_);
    cudaMemsetAsync(p_h16h, 0, sizeof(__half) * B_ * HPAD_);
    cudaMemsetAsync(p_h16l, 0, sizeof(__half) * B_ * HPAD_);
    cudaMemsetAsync(p_y16h, 0, sizeof(__half) * B_ * YPAD_);
    cudaMemsetAsync(p_y16l, 0, sizeof(__half) * B_ * YPAD_);

    // 1) GNN -> seq fp16 ; weight conversions
    gnn_kernel<<<NG_, 256>>>(x, edge_index, edge_f, edge_attr, Wx, We, Wf, Wedge, p_seq);
    {
        size_t t1 = (size_t)G3HP_ * SEQ_;
        conv_wih<<<(int)((t1 + 255) / 256), 256>>>(w_ih, p_wih);
        size_t t2 = (size_t)G3HP_ * HPAD_;
        conv_whh<<<(int)((t2 + 255) / 256), 256>>>(w_hh, p_whh);
        size_t t3 = (size_t)MLP1_ * YPAD_;
        conv_w1t<<<(int)((t3 + 255) / 256), 256>>>(mlp_w1, p_w1t);
    }

    // 2) gi = seq @ w_ih^T + b_ih   [10240, 2400]  (HMMA 1-pass)
    {
        dim3 grid(G3HP_ / 128, NG_ / 128);   // 19 x 80
        gemm_f16<1><<<grid, 256, 2 * 32768>>>(p_seq, nullptr, p_wih, b_ih,
                                              p_gi, NG_, G3H_, SEQ_);
    }

    // 3) GRU recurrence (HMMA 2-pass on h hi/lo)
    {
        dim3 gridh(G3HP_ / 128, B_ / 128);   // 19 x 16
        for (int t = 0; t < S_; t++) {
            gemm_f16<2><<<gridh, 256, 2 * 49152>>>(p_h16h, p_h16l, p_whh, b_hh,
                                                   p_gh, B_, G3H_, HPAD_);
            gru_gate<<<(B_ * H_ + 255) / 256, 256>>>(p_gi, p_gh, p_h,
                                                     p_h16h, p_h16l, p_y16h, p_y16l, t);
        }
    }

    // 4) MLP
    {
        dim3 g1(MLP1_ / 128, B_ / 128);      // 10 x 16
        gemm_f16<2><<<g1, 256, 2 * 49152>>>(p_y16h, p_y16l, p_w1t, mlp_b1,
                                            p_z1, B_, MLP1_, YPAD_);
        dim3 g2((OUTN_ + 127) / 128, B_ / 128);
        sgemm128_nn<<<g2, 256>>>(p_z1, mlp_w2, mlp_b2, out, B_, OUTN_, MLP1_);
    }
}

// round 5
// speedup vs baseline: 3.9087x; 1.3024x over previous
#include <cuda_runtime.h>
#include <cuda_fp16.h>
#include <math.h>
#include <stdint.h>

// ---------------- problem constants ----------------
#define B_   2048
#define S_   5
#define N_   80
#define E_   592
#define FX_  8
#define FF_  4
#define FE_  8
#define D_   8
#define H_   800
#define NG_  (B_ * S_)            // 10240 graphs
#define XDIM_ (N_ * D_)           // 640
#define EDIM_ (E_ * D_)           // 4736
#define SEQ_  (XDIM_ + EDIM_)     // 5376 (= 84 * 64)
#define G3H_  (3 * H_)            // 2400
#define G3HP_ 2432                // padded to 19*128
#define HPAD_ 832                 // 800 padded to 13*64
#define YPAD_ 4032                // 4000 padded to 63*64
#define MLP1_ 1280
#define OUTN_ 400                 // S_*80
#define OUTNP_ 512                // padded to 4*128

// ---------------- scratch (__device__ globals: allocation-free) ----------------
__device__ __align__(128) __half g_seq16[(size_t)NG_ * SEQ_];
__device__ __align__(128) __half g_wih16[(size_t)G3HP_ * SEQ_];
__device__ __align__(128) __half g_whh16[(size_t)G3HP_ * HPAD_];
__device__ __align__(128) __half g_w1t16[(size_t)MLP1_ * YPAD_];
__device__ __align__(128) __half g_w2t16[(size_t)OUTNP_ * MLP1_];
__device__ __align__(128) __half g_h16[(size_t)B_ * HPAD_];
__device__ __align__(128) __half g_y16[(size_t)B_ * YPAD_];
__device__ __align__(128) __half g_z1 [(size_t)B_ * MLP1_];
__device__ float g_gi [(size_t)NG_ * G3H_];
__device__ float g_gh [(size_t)B_  * G3H_];
__device__ float g_h  [(size_t)B_  * H_];

// ---------------- helpers ----------------
__device__ __forceinline__ uint32_t smem_u32(const void* p) {
    uint32_t a;
    asm("{ .reg .u64 t; cvta.to.shared.u64 t, %1; cvt.u32.u64 %0, t; }"
        : "=r"(a) : "l"(p));
    return a;
}
#define SW128(o) ((o) ^ (((o) >> 3) & 0x70))

__device__ __forceinline__ void cp16(uint32_t dst, const void* src) {
    asm volatile("cp.async.cg.shared.global [%0], [%1], 16;" :: "r"(dst), "l"(src));
}
__device__ __forceinline__ void cp_commit() {
    asm volatile("cp.async.commit_group;");
}
__device__ __forceinline__ void cp_wait1() {
    asm volatile("cp.async.wait_group 1;");
}
__device__ __forceinline__ void cp_wait0() {
    asm volatile("cp.async.wait_group 0;");
}
__device__ __forceinline__ void ldm4(uint32_t& r0, uint32_t& r1, uint32_t& r2, uint32_t& r3,
                                     uint32_t addr) {
    asm volatile("ldmatrix.sync.aligned.m8n8.x4.shared.b16 {%0,%1,%2,%3}, [%4];"
                 : "=r"(r0), "=r"(r1), "=r"(r2), "=r"(r3) : "r"(addr));
}
__device__ __forceinline__ void mma16816(float* c, const uint32_t* a, const uint32_t* b) {
    asm volatile(
        "mma.sync.aligned.m16n8k16.row.col.f32.f16.f16.f32 "
        "{%0,%1,%2,%3}, {%4,%5,%6,%7}, {%8,%9}, {%0,%1,%2,%3};"
        : "+f"(c[0]), "+f"(c[1]), "+f"(c[2]), "+f"(c[3])
        : "r"(a[0]), "r"(a[1]), "r"(a[2]), "r"(a[3]), "r"(b[0]), "r"(b[1]));
}

// ---------------- GNN: one block per graph, writes fp16 seq ----------------
__global__ void __launch_bounds__(256) gnn_kernel(
    const float* __restrict__ x, const int* __restrict__ edge_index,
    const float* __restrict__ edge_f, const float* __restrict__ edge_attr,
    const float* __restrict__ Wx, const float* __restrict__ We,
    const float* __restrict__ Wf, const float* __restrict__ Wedge,
    __half* __restrict__ seq16)
{
    const int g = blockIdx.x;
    const int tid = threadIdx.x;

    const float* xg  = x          + (size_t)g * N_ * FX_;
    const int*   ei  = edge_index + (size_t)g * 2 * E_;
    const float* efg = edge_f     + (size_t)g * E_ * FF_;
    const float* eag = edge_attr  + (size_t)g * E_ * FE_;

    __shared__ float sWx[FX_ * D_];
    __shared__ float sWe[FE_ * D_];
    __shared__ float sWf[FF_ * D_];
    __shared__ float sWedge[(2 * D_ + FE_) * D_];
    __shared__ float s_agg[N_ * D_];
    __shared__ float s_xout[N_ * D_];
    __shared__ float s_eag[E_ * FE_];
    __shared__ int   s_src[E_];
    __shared__ int   s_dst[E_];
    __shared__ int   s_min;

    if (tid < FX_ * D_) sWx[tid] = Wx[tid];
    if (tid < FE_ * D_) sWe[tid] = We[tid];
    if (tid < FF_ * D_) sWf[tid] = Wf[tid];
    if (tid < (2 * D_ + FE_) * D_) sWedge[tid] = Wedge[tid];
    for (int i = tid; i < N_ * D_; i += 256) s_agg[i] = 0.f;
    if (tid == 0) s_min = 0x7fffffff;
    __syncthreads();

    int lmin = 0x7fffffff;
    for (int e = tid; e < E_; e += 256) lmin = min(lmin, ei[e]);
    atomicMin(&s_min, lmin);
    __syncthreads();
    const int mn = s_min;

    for (int e = tid; e < E_; e += 256) {
        int sI = ei[e]      - mn;
        int dI = ei[E_ + e] - mn;
        if (dI < 0) dI += N_;     // JAX negative-index wrap
        s_src[e] = sI;
        s_dst[e] = dI;
        float ea[FE_], ef[FF_];
#pragma unroll
        for (int k = 0; k < FE_; k++) { ea[k] = eag[e * FE_ + k]; s_eag[e * FE_ + k] = ea[k]; }
#pragma unroll
        for (int k = 0; k < FF_; k++) ef[k] = efg[e * FF_ + k];
#pragma unroll
        for (int d = 0; d < D_; d++) {
            float m = 0.f;
#pragma unroll
            for (int k = 0; k < FE_; k++) m = fmaf(ea[k], sWe[k * D_ + d], m);
#pragma unroll
            for (int k = 0; k < FF_; k++) m = fmaf(ef[k], sWf[k * D_ + d], m);
            m = fmaxf(m, 0.f);
            atomicAdd(&s_agg[dI * D_ + d], m);
        }
    }
    __syncthreads();

    for (int n = tid; n < N_; n += 256) {
        float xv[FX_];
#pragma unroll
        for (int k = 0; k < FX_; k++) xv[k] = xg[n * FX_ + k];
#pragma unroll
        for (int d = 0; d < D_; d++) {
            float t = s_agg[n * D_ + d];
#pragma unroll
            for (int k = 0; k < FX_; k++) t = fmaf(xv[k], sWx[k * D_ + d], t);
            float xo = xv[d] + fmaxf(t, 0.f);
            s_xout[n * D_ + d] = xo;
            seq16[(size_t)g * SEQ_ + n * D_ + d] = __float2half_rn(xo);
        }
    }
    __syncthreads();

    for (int e = tid; e < E_; e += 256) {
        const int sI = s_src[e], dI = s_dst[e];
        float feat[2 * D_ + FE_];
#pragma unroll
        for (int k = 0; k < D_; k++)  feat[k]          = s_xout[sI * D_ + k];
#pragma unroll
        for (int k = 0; k < D_; k++)  feat[D_ + k]     = s_xout[dI * D_ + k];
#pragma unroll
        for (int k = 0; k < FE_; k++) feat[2 * D_ + k] = s_eag[e * FE_ + k];
#pragma unroll
        for (int d = 0; d < D_; d++) {
            float t = 0.f;
#pragma unroll
            for (int k = 0; k < 2 * D_ + FE_; k++) t = fmaf(feat[k], sWedge[k * D_ + d], t);
            float eo = s_eag[e * FE_ + d] + fmaxf(t, 0.f);
            seq16[(size_t)g * SEQ_ + XDIM_ + e * D_ + d] = __float2half_rn(eo);
        }
    }
}

// ---------------- weight conversion kernels ----------------
__global__ void __launch_bounds__(256) conv_wih(const float* __restrict__ w,
                                                __half* __restrict__ o)
{
    size_t i = (size_t)blockIdx.x * 256 + threadIdx.x;
    if (i >= (size_t)G3HP_ * SEQ_) return;
    int n = (int)(i / SEQ_);
    o[i] = __float2half_rn(n < G3H_ ? w[i] : 0.f);
}
__global__ void __launch_bounds__(256) conv_whh(const float* __restrict__ w,
                                                __half* __restrict__ o)
{
    size_t i = (size_t)blockIdx.x * 256 + threadIdx.x;
    if (i >= (size_t)G3HP_ * HPAD_) return;
    int n = (int)(i / HPAD_);
    int k = (int)(i % HPAD_);
    o[i] = __float2half_rn((n < G3H_ && k < H_) ? w[(size_t)n * H_ + k] : 0.f);
}
__global__ void __launch_bounds__(256) conv_w1t(const float* __restrict__ w,
                                                __half* __restrict__ o)
{
    size_t i = (size_t)blockIdx.x * 256 + threadIdx.x;
    if (i >= (size_t)MLP1_ * YPAD_) return;
    int n = (int)(i / YPAD_);
    int k = (int)(i % YPAD_);
    o[i] = __float2half_rn(k < S_ * H_ ? w[(size_t)k * MLP1_ + n] : 0.f);
}
__global__ void __launch_bounds__(256) conv_w2t(const float* __restrict__ w,
                                                __half* __restrict__ o)
{
    size_t i = (size_t)blockIdx.x * 256 + threadIdx.x;
    if (i >= (size_t)OUTNP_ * MLP1_) return;
    int n = (int)(i / MLP1_);
    int k = (int)(i % MLP1_);
    o[i] = __float2half_rn(n < OUTN_ ? w[(size_t)k * OUTN_ + n] : 0.f);
}

// ---------------- HMMA TN GEMM, 1-pass fp16 ----------------
// C[M,Nn] = A[M,K] @ Bw[Nn,K]^T + bias; fp32 or fp16 output (OUTH).
// K % 64 == 0, M % 128 == 0; Bw row-padded to gridDim.x*128.
// Tile 128x128x64, 2-stage cp.async pipeline, SW128 smem. smem = 64KB.
template <bool OUTH>
__global__ void __launch_bounds__(256) gemm_f16(
    const __half* __restrict__ A, const __half* __restrict__ Bw,
    const float* __restrict__ bias,
    float* __restrict__ C, __half* __restrict__ Ch,
    int M, int Nn, int K)
{
    constexpr int TOFF_B = 16384;
    constexpr int TSTAGE = 32768;

    extern __shared__ char smem[];
    const uint32_t sbase = smem_u32(smem);
    const int tid = threadIdx.x;
    const int wid = tid >> 5, lid = tid & 31;
    const int m0 = blockIdx.y * 128;
    const int n0 = blockIdx.x * 128;

    const int wm = wid & 3;      // 0..3 -> 32-row slab
    const int wn = wid >> 2;     // 0..1 -> 64-col slab

    float acc[2][8][4];
#pragma unroll
    for (int i = 0; i < 2; i++)
#pragma unroll
        for (int j = 0; j < 8; j++)
#pragma unroll
            for (int q = 0; q < 4; q++) acc[i][j][q] = 0.f;

    const int lrow = tid >> 1;
    const int lkc0 = (tid & 1) * 4;

    const int nch = K / 64;

    auto load_stage = [&](int st, int c) {
        const int k0 = c * 64;
        const uint32_t stb = sbase + st * TSTAGE;
#pragma unroll
        for (int i = 0; i < 4; i++) {
            const int kc = lkc0 + i;
            const uint32_t so = SW128((uint32_t)(lrow * 128 + kc * 16));
            cp16(stb + so, A + (size_t)(m0 + lrow) * K + k0 + kc * 8);
            cp16(stb + TOFF_B + so, Bw + (size_t)(n0 + lrow) * K + k0 + kc * 8);
        }
        cp_commit();
    };

    load_stage(0, 0);

    const int lt = lid >> 3;   // ldmatrix tile index 0..3
    const int lr = lid & 7;    // row within tile

    for (int c = 0; c < nch; c++) {
        if (c + 1 < nch) load_stage((c + 1) & 1, c + 1);
        if (c + 1 < nch) cp_wait1(); else cp_wait0();
        __syncthreads();

        const uint32_t stb = sbase + (c & 1) * TSTAGE;
#pragma unroll
        for (int kk = 0; kk < 4; kk++) {
            const int kc = kk * 2 + (lt >> 1);
            uint32_t aH[2][4];
#pragma unroll
            for (int mt = 0; mt < 2; mt++) {
                const int row = wm * 32 + mt * 16 + (lt & 1) * 8 + lr;
                const uint32_t so = SW128((uint32_t)(row * 128 + kc * 16));
                ldm4(aH[mt][0], aH[mt][1], aH[mt][2], aH[mt][3], stb + so);
            }
            uint32_t bf[8][2];
#pragma unroll
            for (int nt = 0; nt < 4; nt++) {
                const int row = wn * 64 + nt * 16 + (lt & 1) * 8 + lr;
                const uint32_t so = SW128((uint32_t)(row * 128 + kc * 16));
                uint32_t q0, q1, q2, q3;
                ldm4(q0, q1, q2, q3, stb + TOFF_B + so);
                bf[nt * 2][0] = q0; bf[nt * 2][1] = q2;
                bf[nt * 2 + 1][0] = q1; bf[nt * 2 + 1][1] = q3;
            }
#pragma unroll
            for (int mt = 0; mt < 2; mt++)
#pragma unroll
                for (int ns = 0; ns < 8; ns++)
                    mma16816(acc[mt][ns], aH[mt], bf[ns]);
        }
        __syncthreads();
    }

    // epilogue
    const int gq = lid >> 2;
    const int tq = lid & 3;
#pragma unroll
    for (int mt = 0; mt < 2; mt++) {
#pragma unroll
        for (int ns = 0; ns < 8; ns++) {
            const int col = n0 + wn * 64 + ns * 8 + tq * 2;
            const int r0 = m0 + wm * 32 + mt * 16 + gq;
#pragma unroll
            for (int dc = 0; dc < 2; dc++) {
                if (col + dc < Nn) {
                    float v0 = acc[mt][ns][dc]     + bias[col + dc];
                    float v1 = acc[mt][ns][2 + dc] + bias[col + dc];
                    if (OUTH) {
                        Ch[(size_t)r0 * Nn + col + dc]       = __float2half_rn(v0);
                        Ch[(size_t)(r0 + 8) * Nn + col + dc] = __float2half_rn(v1);
                    } else {
                        C[(size_t)r0 * Nn + col + dc]       = v0;
                        C[(size_t)(r0 + 8) * Nn + col + dc] = v1;
                    }
                }
            }
        }
    }
}

// ---------------- GRU pointwise gates ----------------
// t == 0: gh is not computed; use gh_bias (b_hh) directly (h=0 -> gh = b_hh).
__global__ void __launch_bounds__(256) gru_gate(
    const float* __restrict__ gi_all, const float* __restrict__ gh,
    const float* __restrict__ gh_bias,
    float* __restrict__ h, __half* __restrict__ h16, __half* __restrict__ y16,
    int t)
{
    const int idx = blockIdx.x * blockDim.x + threadIdx.x;
    if (idx >= B_ * H_) return;
    const int b = idx / H_;
    const int j = idx % H_;

    const float* gi = gi_all + (size_t)(b * S_ + t) * G3H_;

    float hr, hz, hn, hprev;
    if (t == 0) {
        hr = gh_bias[j]; hz = gh_bias[H_ + j]; hn = gh_bias[2 * H_ + j];
        hprev = 0.f;
    } else {
        const float* ghb = gh + (size_t)b * G3H_;
        hr = ghb[j]; hz = ghb[H_ + j]; hn = ghb[2 * H_ + j];
        hprev = h[idx];
    }

    const float ir = gi[j], iz = gi[H_ + j], in = gi[2 * H_ + j];

    const float r = 1.f / (1.f + expf(-(ir + hr)));
    const float z = 1.f / (1.f + expf(-(iz + hz)));
    const float n = tanhf(in + r * hn);

    const float hnew = (1.f - z) * n + z * hprev;
    h[idx] = hnew;

    const __half hv = __float2half_rn(hnew);
    h16[(size_t)b * HPAD_ + j] = hv;
    y16[(size_t)b * YPAD_ + t * H_ + j] = hv;
}

// ---------------- launch ----------------
extern "C" void kernel_launch(void* const* d_in, const int* in_sizes, int n_in,
                              void* d_out, int out_size)
{
    const float* x          = (const float*)d_in[0];
    const int*   edge_index = (const int*)  d_in[1];
    const float* edge_f     = (const float*)d_in[2];
    const float* edge_attr  = (const float*)d_in[3];
    const float* Wx         = (const float*)d_in[4];
    const float* We         = (const float*)d_in[5];
    const float* Wf         = (const float*)d_in[6];
    const float* Wedge      = (const float*)d_in[7];
    const float* w_ih       = (const float*)d_in[8];
    const float* w_hh       = (const float*)d_in[9];
    const float* b_ih       = (const float*)d_in[10];
    const float* b_hh       = (const float*)d_in[11];
    const float* mlp_w1     = (const float*)d_in[12];
    const float* mlp_b1     = (const float*)d_in[13];
    const float* mlp_w2     = (const float*)d_in[14];
    const float* mlp_b2     = (const float*)d_in[15];
    float* out = (float*)d_out;

    __half *p_seq, *p_wih, *p_whh, *p_w1t, *p_w2t, *p_h16, *p_y16, *p_z1;
    float *p_gi, *p_gh, *p_h;
    cudaGetSymbolAddress((void**)&p_seq, g_seq16);
    cudaGetSymbolAddress((void**)&p_wih, g_wih16);
    cudaGetSymbolAddress((void**)&p_whh, g_whh16);
    cudaGetSymbolAddress((void**)&p_w1t, g_w1t16);
    cudaGetSymbolAddress((void**)&p_w2t, g_w2t16);
    cudaGetSymbolAddress((void**)&p_h16, g_h16);
    cudaGetSymbolAddress((void**)&p_y16, g_y16);
    cudaGetSymbolAddress((void**)&p_z1,  g_z1);
    cudaGetSymbolAddress((void**)&p_gi,  g_gi);
    cudaGetSymbolAddress((void**)&p_gh,  g_gh);
    cudaGetSymbolAddress((void**)&p_h,   g_h);

    cudaFuncSetAttribute(gemm_f16<false>, cudaFuncAttributeMaxDynamicSharedMemorySize, 65536);
    cudaFuncSetAttribute(gemm_f16<true>,  cudaFuncAttributeMaxDynamicSharedMemorySize, 65536);

    // 0) zero pads (h16 cols 800..831, y16 cols 4000..4031 must stay zero)
    cudaMemsetAsync(p_h16, 0, sizeof(__half) * B_ * HPAD_);
    cudaMemsetAsync(p_y16, 0, sizeof(__half) * B_ * YPAD_);

    // 1) GNN -> seq fp16 ; weight conversions
    gnn_kernel<<<NG_, 256>>>(x, edge_index, edge_f, edge_attr, Wx, We, Wf, Wedge, p_seq);
    {
        size_t t1 = (size_t)G3HP_ * SEQ_;
        conv_wih<<<(int)((t1 + 255) / 256), 256>>>(w_ih, p_wih);
        size_t t2 = (size_t)G3HP_ * HPAD_;
        conv_whh<<<(int)((t2 + 255) / 256), 256>>>(w_hh, p_whh);
        size_t t3 = (size_t)MLP1_ * YPAD_;
        conv_w1t<<<(int)((t3 + 255) / 256), 256>>>(mlp_w1, p_w1t);
        size_t t4 = (size_t)OUTNP_ * MLP1_;
        conv_w2t<<<(int)((t4 + 255) / 256), 256>>>(mlp_w2, p_w2t);
    }

    // 2) gi = seq @ w_ih^T + b_ih   [10240, 2400]
    {
        dim3 grid(G3HP_ / 128, NG_ / 128);   // 19 x 80
        gemm_f16<false><<<grid, 256, 65536>>>(p_seq, p_wih, b_ih,
                                              p_gi, nullptr, NG_, G3H_, SEQ_);
    }

    // 3) GRU recurrence (t=0 skips the GEMM: gh == b_hh since h=0)
    {
        dim3 gridh(G3HP_ / 128, B_ / 128);   // 19 x 16
        for (int t = 0; t < S_; t++) {
            if (t > 0)
                gemm_f16<false><<<gridh, 256, 65536>>>(p_h16, p_whh, b_hh,
                                                       p_gh, nullptr, B_, G3H_, HPAD_);
            gru_gate<<<(B_ * H_ + 255) / 256, 256>>>(p_gi, p_gh, b_hh,
                                                     p_h, p_h16, p_y16, t);
        }
    }

    // 4) MLP (both layers HMMA; z1 kept fp16 via OUTH epilogue)
    {
        dim3 g1(MLP1_ / 128, B_ / 128);      // 10 x 16
        gemm_f16<true><<<g1, 256, 65536>>>(p_y16, p_w1t, mlp_b1,
                                           nullptr, p_z1, B_, MLP1_, YPAD_);
        dim3 g2(OUTNP_ / 128, B_ / 128);     // 4 x 16
        gemm_f16<false><<<g2, 256, 65536>>>(p_z1, p_w2t, mlp_b2,
                                            out, nullptr, B_, OUTN_, MLP1_);
    }
}

// round 6
// speedup vs baseline: 4.2580x; 1.0894x over previous
#include <cuda_runtime.h>
#include <cuda_fp16.h>
#include <math.h>
#include <stdint.h>

// ---------------- problem constants ----------------
#define B_   2048
#define S_   5
#define N_   80
#define E_   592
#define FX_  8
#define FF_  4
#define FE_  8
#define D_   8
#define H_   800
#define NG_  (B_ * S_)            // 10240 graphs
#define XDIM_ (N_ * D_)           // 640
#define EDIM_ (E_ * D_)           // 4736
#define SEQ_  (XDIM_ + EDIM_)     // 5376 (= 84 * 64)
#define G3H_  (3 * H_)            // 2400
#define G3HP_ 2432                // padded to 19*128
#define HPAD_ 832                 // 800 padded to 13*64
#define YPAD_ 4032                // 4000 padded to 63*64
#define MLP1_ 1280
#define OUTN_ 400                 // S_*80
#define OUTNP_ 512                // padded to 4*128

// ---------------- scratch (__device__ globals: allocation-free) ----------------
__device__ __align__(128) __half g_seq16[(size_t)NG_ * SEQ_];
__device__ __align__(128) __half g_wih16[(size_t)G3HP_ * SEQ_];
__device__ __align__(128) __half g_whh16[(size_t)G3HP_ * HPAD_];
__device__ __align__(128) __half g_w1t16[(size_t)MLP1_ * YPAD_];
__device__ __align__(128) __half g_w2t16[(size_t)OUTNP_ * MLP1_];
__device__ __align__(128) __half g_h16[(size_t)B_ * HPAD_];
__device__ __align__(128) __half g_y16[(size_t)B_ * YPAD_];
__device__ __align__(128) __half g_z1 [(size_t)B_ * MLP1_];
__device__ float g_gi [(size_t)NG_ * G3H_];
__device__ float g_gh [(size_t)B_  * G3H_];
__device__ float g_h  [(size_t)B_  * H_];

// ---------------- helpers ----------------
__device__ __forceinline__ uint32_t smem_u32(const void* p) {
    uint32_t a;
    asm("{ .reg .u64 t; cvta.to.shared.u64 t, %1; cvt.u32.u64 %0, t; }"
        : "=r"(a) : "l"(p));
    return a;
}
#define SW128(o) ((o) ^ (((o) >> 3) & 0x70))

__device__ __forceinline__ void cp16(uint32_t dst, const void* src) {
    asm volatile("cp.async.cg.shared.global [%0], [%1], 16;" :: "r"(dst), "l"(src));
}
__device__ __forceinline__ void cp_commit() {
    asm volatile("cp.async.commit_group;");
}
__device__ __forceinline__ void cp_wait1() {
    asm volatile("cp.async.wait_group 1;");
}
__device__ __forceinline__ void cp_wait0() {
    asm volatile("cp.async.wait_group 0;");
}
__device__ __forceinline__ void ldm4(uint32_t& r0, uint32_t& r1, uint32_t& r2, uint32_t& r3,
                                     uint32_t addr) {
    asm volatile("ldmatrix.sync.aligned.m8n8.x4.shared.b16 {%0,%1,%2,%3}, [%4];"
                 : "=r"(r0), "=r"(r1), "=r"(r2), "=r"(r3) : "r"(addr));
}
__device__ __forceinline__ void mma16816(float* c, const uint32_t* a, const uint32_t* b) {
    asm volatile(
        "mma.sync.aligned.m16n8k16.row.col.f32.f16.f16.f32 "
        "{%0,%1,%2,%3}, {%4,%5,%6,%7}, {%8,%9}, {%0,%1,%2,%3};"
        : "+f"(c[0]), "+f"(c[1]), "+f"(c[2]), "+f"(c[3])
        : "r"(a[0]), "r"(a[1]), "r"(a[2]), "r"(a[3]), "r"(b[0]), "r"(b[1]));
}

// ---------------- GNN: CSR-gather version (few shared atomics) ----------------
__global__ void __launch_bounds__(256) gnn_kernel(
    const float* __restrict__ x, const int* __restrict__ edge_index,
    const float* __restrict__ edge_f, const float* __restrict__ edge_attr,
    const float* __restrict__ Wx, const float* __restrict__ We,
    const float* __restrict__ Wf, const float* __restrict__ Wedge,
    __half* __restrict__ seq16)
{
    const int g = blockIdx.x;
    const int tid = threadIdx.x;

    const float* xg  = x          + (size_t)g * N_ * FX_;
    const int*   ei  = edge_index + (size_t)g * 2 * E_;
    const float* efg = edge_f     + (size_t)g * E_ * FF_;
    const float* eag = edge_attr  + (size_t)g * E_ * FE_;

    __shared__ float sWx[FX_ * D_];
    __shared__ float sWe[FE_ * D_];
    __shared__ float sWf[FF_ * D_];
    __shared__ float sWedge[(2 * D_ + FE_) * D_];
    __shared__ float s_msg[E_ * D_];        // edge messages (18.5 KB)
    __shared__ float s_eag[E_ * FE_];       // edge_attr copy (18.5 KB)
    __shared__ float s_xout[N_ * D_];
    __shared__ short s_src[E_];
    __shared__ short s_dst[E_];
    __shared__ short s_perm[E_];            // edge ids sorted by dst
    __shared__ int   s_cnt[128];            // per-node in-degree (padded)
    __shared__ int   s_tmp[128];
    __shared__ int   s_start[128];          // exclusive scan
    __shared__ int   s_ofs[N_];
    __shared__ int   s_min;

    if (tid < FX_ * D_) sWx[tid] = Wx[tid];
    if (tid < FE_ * D_) sWe[tid] = We[tid];
    if (tid < FF_ * D_) sWf[tid] = Wf[tid];
    if (tid < (2 * D_ + FE_) * D_) sWedge[tid] = Wedge[tid];
    if (tid < 128) s_cnt[tid] = 0;
    if (tid == 0) s_min = 0x7fffffff;
    __syncthreads();

    int lmin = 0x7fffffff;
    for (int e = tid; e < E_; e += 256) lmin = min(lmin, ei[e]);
    atomicMin(&s_min, lmin);
    __syncthreads();
    const int mn = s_min;

    // Phase A: edge messages (no node atomics) + in-degree counts
    for (int e = tid; e < E_; e += 256) {
        int sI = ei[e]      - mn;
        int dI = ei[E_ + e] - mn;
        if (dI < 0) dI += N_;     // JAX negative-index wrap
        s_src[e] = (short)sI;
        s_dst[e] = (short)dI;
        atomicAdd(&s_cnt[dI], 1);
        float ea[FE_], ef[FF_];
#pragma unroll
        for (int k = 0; k < FE_; k++) { ea[k] = eag[e * FE_ + k]; s_eag[e * FE_ + k] = ea[k]; }
#pragma unroll
        for (int k = 0; k < FF_; k++) ef[k] = efg[e * FF_ + k];
#pragma unroll
        for (int d = 0; d < D_; d++) {
            float m = 0.f;
#pragma unroll
            for (int k = 0; k < FE_; k++) m = fmaf(ea[k], sWe[k * D_ + d], m);
#pragma unroll
            for (int k = 0; k < FF_; k++) m = fmaf(ef[k], sWf[k * D_ + d], m);
            s_msg[e * D_ + d] = fmaxf(m, 0.f);
        }
    }
    __syncthreads();

    // Exclusive scan of s_cnt[0..127] (Hillis-Steele, 128 threads)
    if (tid < 128) s_tmp[tid] = s_cnt[tid];
    __syncthreads();
#pragma unroll
    for (int off = 1; off < 128; off <<= 1) {
        int v = 0;
        if (tid < 128) {
            v = s_tmp[tid];
            if (tid >= off) v += s_tmp[tid - off];
        }
        __syncthreads();
        if (tid < 128) s_tmp[tid] = v;
        __syncthreads();
    }
    if (tid < 128) s_start[tid] = (tid == 0) ? 0 : s_tmp[tid - 1];
    if (tid < N_) s_ofs[tid] = (tid == 0) ? 0 : s_tmp[tid - 1];
    __syncthreads();

    // Phase B: counting-sort edge ids by dst
    for (int e = tid; e < E_; e += 256) {
        int pos = atomicAdd(&s_ofs[(int)s_dst[e]], 1);
        s_perm[pos] = (short)e;
    }
    __syncthreads();

    // Phase C: node update via gather (one thread per (node, d))
    for (int task = tid; task < N_ * D_; task += 256) {
        const int n = task >> 3;
        const int d = task & 7;
        float agg = 0.f;
        const int s0 = s_start[n];
        const int s1 = s_start[n + 1];
        for (int i = s0; i < s1; i++)
            agg += s_msg[(int)s_perm[i] * D_ + d];
        float t = agg;
#pragma unroll
        for (int k = 0; k < FX_; k++) t = fmaf(xg[n * FX_ + k], sWx[k * D_ + d], t);
        float xo = xg[n * FX_ + d] + fmaxf(t, 0.f);
        s_xout[n * D_ + d] = xo;
        seq16[(size_t)g * SEQ_ + n * D_ + d] = __float2half_rn(xo);
    }
    __syncthreads();

    // Phase D: edge update (residual)
    for (int e = tid; e < E_; e += 256) {
        const int sI = (int)s_src[e], dI = (int)s_dst[e];
        float feat[2 * D_ + FE_];
#pragma unroll
        for (int k = 0; k < D_; k++)  feat[k]          = s_xout[sI * D_ + k];
#pragma unroll
        for (int k = 0; k < D_; k++)  feat[D_ + k]     = s_xout[dI * D_ + k];
#pragma unroll
        for (int k = 0; k < FE_; k++) feat[2 * D_ + k] = s_eag[e * FE_ + k];
#pragma unroll
        for (int d = 0; d < D_; d++) {
            float t = 0.f;
#pragma unroll
            for (int k = 0; k < 2 * D_ + FE_; k++) t = fmaf(feat[k], sWedge[k * D_ + d], t);
            float eo = s_eag[e * FE_ + d] + fmaxf(t, 0.f);
            seq16[(size_t)g * SEQ_ + XDIM_ + e * D_ + d] = __float2half_rn(eo);
        }
    }
}

// ---------------- fused weight conversion (all 4 weights, 1 launch) ----------------
#define NB_WIH ((G3HP_ * SEQ_ + 255) / 256)            // 51072
#define NB_WHH ((G3HP_ * HPAD_ + 255) / 256)           // 7904
#define NB_W1T ((MLP1_ * YPAD_ + 255) / 256)           // 20160
#define NB_W2T ((OUTNP_ * MLP1_ + 255) / 256)          // 2560
#define NB_ALL (NB_WIH + NB_WHH + NB_W1T + NB_W2T)

__global__ void __launch_bounds__(256) conv_all(
    const float* __restrict__ w_ih, const float* __restrict__ w_hh,
    const float* __restrict__ mlp_w1, const float* __restrict__ mlp_w2,
    __half* __restrict__ o_wih, __half* __restrict__ o_whh,
    __half* __restrict__ o_w1t, __half* __restrict__ o_w2t)
{
    int b = blockIdx.x;
    if (b < NB_WIH) {
        size_t i = (size_t)b * 256 + threadIdx.x;
        if (i < (size_t)G3HP_ * SEQ_) {
            int n = (int)(i / SEQ_);
            o_wih[i] = __float2half_rn(n < G3H_ ? w_ih[i] : 0.f);
        }
        return;
    }
    b -= NB_WIH;
    if (b < NB_WHH) {
        size_t i = (size_t)b * 256 + threadIdx.x;
        if (i < (size_t)G3HP_ * HPAD_) {
            int n = (int)(i / HPAD_);
            int k = (int)(i % HPAD_);
            o_whh[i] = __float2half_rn((n < G3H_ && k < H_) ? w_hh[(size_t)n * H_ + k] : 0.f);
        }
        return;
    }
    b -= NB_WHH;
    if (b < NB_W1T) {
        size_t i = (size_t)b * 256 + threadIdx.x;
        if (i < (size_t)MLP1_ * YPAD_) {
            int n = (int)(i / YPAD_);
            int k = (int)(i % YPAD_);
            o_w1t[i] = __float2half_rn(k < S_ * H_ ? mlp_w1[(size_t)k * MLP1_ + n] : 0.f);
        }
        return;
    }
    b -= NB_W1T;
    {
        size_t i = (size_t)b * 256 + threadIdx.x;
        if (i < (size_t)OUTNP_ * MLP1_) {
            int n = (int)(i / MLP1_);
            int k = (int)(i % MLP1_);
            o_w2t[i] = __float2half_rn(n < OUTN_ ? mlp_w2[(size_t)k * OUTN_ + n] : 0.f);
        }
    }
}

// ---------------- HMMA TN GEMM, 1-pass fp16 ----------------
// C[M,Nn] = A[M,K] @ Bw[Nn,K]^T + bias; fp32 or fp16 output (OUTH).
// K % 64 == 0, M % 128 == 0; Bw row-padded to gridDim.x*128.
// Tile 128x128x64, 2-stage cp.async pipeline, SW128 smem. smem = 64KB.
template <bool OUTH>
__global__ void __launch_bounds__(256) gemm_f16(
    const __half* __restrict__ A, const __half* __restrict__ Bw,
    const float* __restrict__ bias,
    float* __restrict__ C, __half* __restrict__ Ch,
    int M, int Nn, int K)
{
    constexpr int TOFF_B = 16384;
    constexpr int TSTAGE = 32768;

    extern __shared__ char smem[];
    const uint32_t sbase = smem_u32(smem);
    const int tid = threadIdx.x;
    const int wid = tid >> 5, lid = tid & 31;
    const int m0 = blockIdx.y * 128;
    const int n0 = blockIdx.x * 128;

    const int wm = wid & 3;      // 0..3 -> 32-row slab
    const int wn = wid >> 2;     // 0..1 -> 64-col slab

    float acc[2][8][4];
#pragma unroll
    for (int i = 0; i < 2; i++)
#pragma unroll
        for (int j = 0; j < 8; j++)
#pragma unroll
            for (int q = 0; q < 4; q++) acc[i][j][q] = 0.f;

    const int lrow = tid >> 1;
    const int lkc0 = (tid & 1) * 4;

    const int nch = K / 64;

    auto load_stage = [&](int st, int c) {
        const int k0 = c * 64;
        const uint32_t stb = sbase + st * TSTAGE;
#pragma unroll
        for (int i = 0; i < 4; i++) {
            const int kc = lkc0 + i;
            const uint32_t so = SW128((uint32_t)(lrow * 128 + kc * 16));
            cp16(stb + so, A + (size_t)(m0 + lrow) * K + k0 + kc * 8);
            cp16(stb + TOFF_B + so, Bw + (size_t)(n0 + lrow) * K + k0 + kc * 8);
        }
        cp_commit();
    };

    load_stage(0, 0);

    const int lt = lid >> 3;   // ldmatrix tile index 0..3
    const int lr = lid & 7;    // row within tile

    for (int c = 0; c < nch; c++) {
        if (c + 1 < nch) load_stage((c + 1) & 1, c + 1);
        if (c + 1 < nch) cp_wait1(); else cp_wait0();
        __syncthreads();

        const uint32_t stb = sbase + (c & 1) * TSTAGE;
#pragma unroll
        for (int kk = 0; kk < 4; kk++) {
            const int kc = kk * 2 + (lt >> 1);
            uint32_t aH[2][4];
#pragma unroll
            for (int mt = 0; mt < 2; mt++) {
                const int row = wm * 32 + mt * 16 + (lt & 1) * 8 + lr;
                const uint32_t so = SW128((uint32_t)(row * 128 + kc * 16));
                ldm4(aH[mt][0], aH[mt][1], aH[mt][2], aH[mt][3], stb + so);
            }
            uint32_t bf[8][2];
#pragma unroll
            for (int nt = 0; nt < 4; nt++) {
                const int row = wn * 64 + nt * 16 + (lt & 1) * 8 + lr;
                const uint32_t so = SW128((uint32_t)(row * 128 + kc * 16));
                uint32_t q0, q1, q2, q3;
                ldm4(q0, q1, q2, q3, stb + TOFF_B + so);
                bf[nt * 2][0] = q0; bf[nt * 2][1] = q2;
                bf[nt * 2 + 1][0] = q1; bf[nt * 2 + 1][1] = q3;
            }
#pragma unroll
            for (int mt = 0; mt < 2; mt++)
#pragma unroll
                for (int ns = 0; ns < 8; ns++)
                    mma16816(acc[mt][ns], aH[mt], bf[ns]);
        }
        __syncthreads();
    }

    // epilogue
    const int gq = lid >> 2;
    const int tq = lid & 3;
#pragma unroll
    for (int mt = 0; mt < 2; mt++) {
#pragma unroll
        for (int ns = 0; ns < 8; ns++) {
            const int col = n0 + wn * 64 + ns * 8 + tq * 2;
            const int r0 = m0 + wm * 32 + mt * 16 + gq;
#pragma unroll
            for (int dc = 0; dc < 2; dc++) {
                if (col + dc < Nn) {
                    float v0 = acc[mt][ns][dc]     + bias[col + dc];
                    float v1 = acc[mt][ns][2 + dc] + bias[col + dc];
                    if (OUTH) {
                        Ch[(size_t)r0 * Nn + col + dc]       = __float2half_rn(v0);
                        Ch[(size_t)(r0 + 8) * Nn + col + dc] = __float2half_rn(v1);
                    } else {
                        C[(size_t)r0 * Nn + col + dc]       = v0;
                        C[(size_t)(r0 + 8) * Nn + col + dc] = v1;
                    }
                }
            }
        }
    }
}

// ---------------- GRU pointwise gates ----------------
// t == 0: gh is not computed; use gh_bias (b_hh) directly (h=0 -> gh = b_hh).
__global__ void __launch_bounds__(256) gru_gate(
    const float* __restrict__ gi_all, const float* __restrict__ gh,
    const float* __restrict__ gh_bias,
    float* __restrict__ h, __half* __restrict__ h16, __half* __restrict__ y16,
    int t)
{
    const int idx = blockIdx.x * blockDim.x + threadIdx.x;
    if (idx >= B_ * H_) return;
    const int b = idx / H_;
    const int j = idx % H_;

    const float* gi = gi_all + (size_t)(b * S_ + t) * G3H_;

    float hr, hz, hn, hprev;
    if (t == 0) {
        hr = gh_bias[j]; hz = gh_bias[H_ + j]; hn = gh_bias[2 * H_ + j];
        hprev = 0.f;
    } else {
        const float* ghb = gh + (size_t)b * G3H_;
        hr = ghb[j]; hz = ghb[H_ + j]; hn = ghb[2 * H_ + j];
        hprev = h[idx];
    }

    const float ir = gi[j], iz = gi[H_ + j], in = gi[2 * H_ + j];

    const float r = 1.f / (1.f + expf(-(ir + hr)));
    const float z = 1.f / (1.f + expf(-(iz + hz)));
    const float n = tanhf(in + r * hn);

    const float hnew = (1.f - z) * n + z * hprev;
    h[idx] = hnew;

    const __half hv = __float2half_rn(hnew);
    h16[(size_t)b * HPAD_ + j] = hv;
    y16[(size_t)b * YPAD_ + t * H_ + j] = hv;
}

// ---------------- launch ----------------
extern "C" void kernel_launch(void* const* d_in, const int* in_sizes, int n_in,
                              void* d_out, int out_size)
{
    const float* x          = (const float*)d_in[0];
    const int*   edge_index = (const int*)  d_in[1];
    const float* edge_f     = (const float*)d_in[2];
    const float* edge_attr  = (const float*)d_in[3];
    const float* Wx         = (const float*)d_in[4];
    const float* We         = (const float*)d_in[5];
    const float* Wf         = (const float*)d_in[6];
    const float* Wedge      = (const float*)d_in[7];
    const float* w_ih       = (const float*)d_in[8];
    const float* w_hh       = (const float*)d_in[9];
    const float* b_ih       = (const float*)d_in[10];
    const float* b_hh       = (const float*)d_in[11];
    const float* mlp_w1     = (const float*)d_in[12];
    const float* mlp_b1     = (const float*)d_in[13];
    const float* mlp_w2     = (const float*)d_in[14];
    const float* mlp_b2     = (const float*)d_in[15];
    float* out = (float*)d_out;

    __half *p_seq, *p_wih, *p_whh, *p_w1t, *p_w2t, *p_h16, *p_y16, *p_z1;
    float *p_gi, *p_gh, *p_h;
    cudaGetSymbolAddress((void**)&p_seq, g_seq16);
    cudaGetSymbolAddress((void**)&p_wih, g_wih16);
    cudaGetSymbolAddress((void**)&p_whh, g_whh16);
    cudaGetSymbolAddress((void**)&p_w1t, g_w1t16);
    cudaGetSymbolAddress((void**)&p_w2t, g_w2t16);
    cudaGetSymbolAddress((void**)&p_h16, g_h16);
    cudaGetSymbolAddress((void**)&p_y16, g_y16);
    cudaGetSymbolAddress((void**)&p_z1,  g_z1);
    cudaGetSymbolAddress((void**)&p_gi,  g_gi);
    cudaGetSymbolAddress((void**)&p_gh,  g_gh);
    cudaGetSymbolAddress((void**)&p_h,   g_h);

    cudaFuncSetAttribute(gemm_f16<false>, cudaFuncAttributeMaxDynamicSharedMemorySize, 65536);
    cudaFuncSetAttribute(gemm_f16<true>,  cudaFuncAttributeMaxDynamicSharedMemorySize, 65536);

    // 0) zero pads (h16 cols 800..831, y16 cols 4000..4031 must stay zero)
    cudaMemsetAsync(p_h16, 0, sizeof(__half) * B_ * HPAD_);
    cudaMemsetAsync(p_y16, 0, sizeof(__half) * B_ * YPAD_);

    // 1) GNN -> seq fp16 ; fused weight conversion
    gnn_kernel<<<NG_, 256>>>(x, edge_index, edge_f, edge_attr, Wx, We, Wf, Wedge, p_seq);
    conv_all<<<NB_ALL, 256>>>(w_ih, w_hh, mlp_w1, mlp_w2, p_wih, p_whh, p_w1t, p_w2t);

    // 2) gi = seq @ w_ih^T + b_ih   [10240, 2400]
    {
        dim3 grid(G3HP_ / 128, NG_ / 128);   // 19 x 80
        gemm_f16<false><<<grid, 256, 65536>>>(p_seq, p_wih, b_ih,
                                              p_gi, nullptr, NG_, G3H_, SEQ_);
    }

    // 3) GRU recurrence (t=0 skips the GEMM: gh == b_hh since h=0)
    {
        dim3 gridh(G3HP_ / 128, B_ / 128);   // 19 x 16
        for (int t = 0; t < S_; t++) {
            if (t > 0)
                gemm_f16<false><<<gridh, 256, 65536>>>(p_h16, p_whh, b_hh,
                                                       p_gh, nullptr, B_, G3H_, HPAD_);
            gru_gate<<<(B_ * H_ + 255) / 256, 256>>>(p_gi, p_gh, b_hh,
                                                     p_h, p_h16, p_y16, t);
        }
    }

    // 4) MLP (both layers HMMA; z1 kept fp16 via OUTH epilogue)
    {
        dim3 g1(MLP1_ / 128, B_ / 128);      // 10 x 16
        gemm_f16<true><<<g1, 256, 65536>>>(p_y16, p_w1t, mlp_b1,
                                           nullptr, p_z1, B_, MLP1_, YPAD_);
        dim3 g2(OUTNP_ / 128, B_ / 128);     // 4 x 16
        gemm_f16<false><<<g2, 256, 65536>>>(p_z1, p_w2t, mlp_b2,
                                            out, nullptr, B_, OUTN_, MLP1_);
    }
}

// round 7
// speedup vs baseline: 4.3094x; 1.0121x over previous
#include <cuda_runtime.h>
#include <cuda_fp16.h>
#include <math.h>
#include <stdint.h>

// ---------------- problem constants ----------------
#define B_   2048
#define S_   5
#define N_   80
#define E_   592
#define FX_  8
#define FF_  4
#define FE_  8
#define D_   8
#define H_   800
#define NG_  (B_ * S_)            // 10240 graphs
#define XDIM_ (N_ * D_)           // 640
#define EDIM_ (E_ * D_)           // 4736
#define SEQ_  (XDIM_ + EDIM_)     // 5376 (= 84 * 64)
#define G3H_  (3 * H_)            // 2400
#define G3HP_ 2432                // padded to 19*128
#define HPAD_ 832                 // 800 padded to 13*64
#define YPAD_ 4032                // 4000 padded to 63*64
#define MLP1_ 1280
#define OUTN_ 400                 // S_*80
#define OUTNP_ 512                // padded to 4*128

// ---------------- scratch (__device__ globals: allocation-free) ----------------
__device__ __align__(128) __half g_seq16[(size_t)NG_ * SEQ_];
__device__ __align__(128) __half g_wih16[(size_t)G3HP_ * SEQ_];
__device__ __align__(128) __half g_whh16[(size_t)G3HP_ * HPAD_];
__device__ __align__(128) __half g_w1t16[(size_t)MLP1_ * YPAD_];
__device__ __align__(128) __half g_w2t16[(size_t)OUTNP_ * MLP1_];
__device__ __align__(128) __half g_h16[(size_t)B_ * HPAD_];
__device__ __align__(128) __half g_y16[(size_t)B_ * YPAD_];
__device__ __align__(128) __half g_z1 [(size_t)B_ * MLP1_];
__device__ float g_gi [(size_t)NG_ * G3H_];
__device__ float g_gh [(size_t)B_  * G3H_];
__device__ float g_h  [(size_t)B_  * H_];

// ---------------- helpers ----------------
__device__ __forceinline__ uint32_t smem_u32(const void* p) {
    uint32_t a;
    asm("{ .reg .u64 t; cvta.to.shared.u64 t, %1; cvt.u32.u64 %0, t; }"
        : "=r"(a) : "l"(p));
    return a;
}
#define SW128(o) ((o) ^ (((o) >> 3) & 0x70))

__device__ __forceinline__ void cp16(uint32_t dst, const void* src) {
    asm volatile("cp.async.cg.shared.global [%0], [%1], 16;" :: "r"(dst), "l"(src));
}
__device__ __forceinline__ void cp_commit() {
    asm volatile("cp.async.commit_group;");
}
__device__ __forceinline__ void ldm4(uint32_t& r0, uint32_t& r1, uint32_t& r2, uint32_t& r3,
                                     uint32_t addr) {
    asm volatile("ldmatrix.sync.aligned.m8n8.x4.shared.b16 {%0,%1,%2,%3}, [%4];"
                 : "=r"(r0), "=r"(r1), "=r"(r2), "=r"(r3) : "r"(addr));
}
__device__ __forceinline__ void mma16816(float* c, const uint32_t* a, const uint32_t* b) {
    asm volatile(
        "mma.sync.aligned.m16n8k16.row.col.f32.f16.f16.f32 "
        "{%0,%1,%2,%3}, {%4,%5,%6,%7}, {%8,%9}, {%0,%1,%2,%3};"
        : "+f"(c[0]), "+f"(c[1]), "+f"(c[2]), "+f"(c[3])
        : "r"(a[0]), "r"(a[1]), "r"(a[2]), "r"(a[3]), "r"(b[0]), "r"(b[1]));
}

// ---------------- GNN: CSR-gather version (few shared atomics) ----------------
__global__ void __launch_bounds__(256) gnn_kernel(
    const float* __restrict__ x, const int* __restrict__ edge_index,
    const float* __restrict__ edge_f, const float* __restrict__ edge_attr,
    const float* __restrict__ Wx, const float* __restrict__ We,
    const float* __restrict__ Wf, const float* __restrict__ Wedge,
    __half* __restrict__ seq16)
{
    const int g = blockIdx.x;
    const int tid = threadIdx.x;

    const float* xg  = x          + (size_t)g * N_ * FX_;
    const int*   ei  = edge_index + (size_t)g * 2 * E_;
    const float* efg = edge_f     + (size_t)g * E_ * FF_;
    const float* eag = edge_attr  + (size_t)g * E_ * FE_;

    __shared__ float sWx[FX_ * D_];
    __shared__ float sWe[FE_ * D_];
    __shared__ float sWf[FF_ * D_];
    __shared__ float sWedge[(2 * D_ + FE_) * D_];
    __shared__ float s_msg[E_ * D_];
    __shared__ float s_eag[E_ * FE_];
    __shared__ float s_xout[N_ * D_];
    __shared__ short s_src[E_];
    __shared__ short s_dst[E_];
    __shared__ short s_perm[E_];
    __shared__ int   s_cnt[128];
    __shared__ int   s_tmp[128];
    __shared__ int   s_start[128];
    __shared__ int   s_ofs[N_];
    __shared__ int   s_min;

    if (tid < FX_ * D_) sWx[tid] = Wx[tid];
    if (tid < FE_ * D_) sWe[tid] = We[tid];
    if (tid < FF_ * D_) sWf[tid] = Wf[tid];
    if (tid < (2 * D_ + FE_) * D_) sWedge[tid] = Wedge[tid];
    if (tid < 128) s_cnt[tid] = 0;
    if (tid == 0) s_min = 0x7fffffff;
    __syncthreads();

    int lmin = 0x7fffffff;
    for (int e = tid; e < E_; e += 256) lmin = min(lmin, ei[e]);
    atomicMin(&s_min, lmin);
    __syncthreads();
    const int mn = s_min;

    // Phase A: edge messages + in-degree counts
    for (int e = tid; e < E_; e += 256) {
        int sI = ei[e]      - mn;
        int dI = ei[E_ + e] - mn;
        if (dI < 0) dI += N_;     // JAX negative-index wrap
        s_src[e] = (short)sI;
        s_dst[e] = (short)dI;
        atomicAdd(&s_cnt[dI], 1);
        float ea[FE_], ef[FF_];
#pragma unroll
        for (int k = 0; k < FE_; k++) { ea[k] = eag[e * FE_ + k]; s_eag[e * FE_ + k] = ea[k]; }
#pragma unroll
        for (int k = 0; k < FF_; k++) ef[k] = efg[e * FF_ + k];
#pragma unroll
        for (int d = 0; d < D_; d++) {
            float m = 0.f;
#pragma unroll
            for (int k = 0; k < FE_; k++) m = fmaf(ea[k], sWe[k * D_ + d], m);
#pragma unroll
            for (int k = 0; k < FF_; k++) m = fmaf(ef[k], sWf[k * D_ + d], m);
            s_msg[e * D_ + d] = fmaxf(m, 0.f);
        }
    }
    __syncthreads();

    // Exclusive scan of s_cnt[0..127]
    if (tid < 128) s_tmp[tid] = s_cnt[tid];
    __syncthreads();
#pragma unroll
    for (int off = 1; off < 128; off <<= 1) {
        int v = 0;
        if (tid < 128) {
            v = s_tmp[tid];
            if (tid >= off) v += s_tmp[tid - off];
        }
        __syncthreads();
        if (tid < 128) s_tmp[tid] = v;
        __syncthreads();
    }
    if (tid < 128) s_start[tid] = (tid == 0) ? 0 : s_tmp[tid - 1];
    if (tid < N_) s_ofs[tid] = (tid == 0) ? 0 : s_tmp[tid - 1];
    __syncthreads();

    // Phase B: counting-sort edge ids by dst
    for (int e = tid; e < E_; e += 256) {
        int pos = atomicAdd(&s_ofs[(int)s_dst[e]], 1);
        s_perm[pos] = (short)e;
    }
    __syncthreads();

    // Phase C: node update via gather
    for (int task = tid; task < N_ * D_; task += 256) {
        const int n = task >> 3;
        const int d = task & 7;
        float agg = 0.f;
        const int s0 = s_start[n];
        const int s1 = s_start[n + 1];
        for (int i = s0; i < s1; i++)
            agg += s_msg[(int)s_perm[i] * D_ + d];
        float t = agg;
#pragma unroll
        for (int k = 0; k < FX_; k++) t = fmaf(xg[n * FX_ + k], sWx[k * D_ + d], t);
        float xo = xg[n * FX_ + d] + fmaxf(t, 0.f);
        s_xout[n * D_ + d] = xo;
        seq16[(size_t)g * SEQ_ + n * D_ + d] = __float2half_rn(xo);
    }
    __syncthreads();

    // Phase D: edge update (residual)
    for (int e = tid; e < E_; e += 256) {
        const int sI = (int)s_src[e], dI = (int)s_dst[e];
        float feat[2 * D_ + FE_];
#pragma unroll
        for (int k = 0; k < D_; k++)  feat[k]          = s_xout[sI * D_ + k];
#pragma unroll
        for (int k = 0; k < D_; k++)  feat[D_ + k]     = s_xout[dI * D_ + k];
#pragma unroll
        for (int k = 0; k < FE_; k++) feat[2 * D_ + k] = s_eag[e * FE_ + k];
#pragma unroll
        for (int d = 0; d < D_; d++) {
            float t = 0.f;
#pragma unroll
            for (int k = 0; k < 2 * D_ + FE_; k++) t = fmaf(feat[k], sWedge[k * D_ + d], t);
            float eo = s_eag[e * FE_ + d] + fmaxf(t, 0.f);
            seq16[(size_t)g * SEQ_ + XDIM_ + e * D_ + d] = __float2half_rn(eo);
        }
    }
}

// ---------------- fused weight conversion (all 4 weights, 1 launch) ----------------
#define NB_WIH ((G3HP_ * SEQ_ + 255) / 256)
#define NB_WHH ((G3HP_ * HPAD_ + 255) / 256)
#define NB_W1T ((MLP1_ * YPAD_ + 255) / 256)
#define NB_W2T ((OUTNP_ * MLP1_ + 255) / 256)
#define NB_ALL (NB_WIH + NB_WHH + NB_W1T + NB_W2T)

__global__ void __launch_bounds__(256) conv_all(
    const float* __restrict__ w_ih, const float* __restrict__ w_hh,
    const float* __restrict__ mlp_w1, const float* __restrict__ mlp_w2,
    __half* __restrict__ o_wih, __half* __restrict__ o_whh,
    __half* __restrict__ o_w1t, __half* __restrict__ o_w2t)
{
    int b = blockIdx.x;
    if (b < NB_WIH) {
        size_t i = (size_t)b * 256 + threadIdx.x;
        if (i < (size_t)G3HP_ * SEQ_) {
            int n = (int)(i / SEQ_);
            o_wih[i] = __float2half_rn(n < G3H_ ? w_ih[i] : 0.f);
        }
        return;
    }
    b -= NB_WIH;
    if (b < NB_WHH) {
        size_t i = (size_t)b * 256 + threadIdx.x;
        if (i < (size_t)G3HP_ * HPAD_) {
            int n = (int)(i / HPAD_);
            int k = (int)(i % HPAD_);
            o_whh[i] = __float2half_rn((n < G3H_ && k < H_) ? w_hh[(size_t)n * H_ + k] : 0.f);
        }
        return;
    }
    b -= NB_WHH;
    if (b < NB_W1T) {
        size_t i = (size_t)b * 256 + threadIdx.x;
        if (i < (size_t)MLP1_ * YPAD_) {
            int n = (int)(i / YPAD_);
            int k = (int)(i % YPAD_);
            o_w1t[i] = __float2half_rn(k < S_ * H_ ? mlp_w1[(size_t)k * MLP1_ + n] : 0.f);
        }
        return;
    }
    b -= NB_W1T;
    {
        size_t i = (size_t)b * 256 + threadIdx.x;
        if (i < (size_t)OUTNP_ * MLP1_) {
            int n = (int)(i / MLP1_);
            int k = (int)(i % MLP1_);
            o_w2t[i] = __float2half_rn(n < OUTN_ ? mlp_w2[(size_t)k * OUTN_ + n] : 0.f);
        }
    }
}

// ---------------- HMMA TN GEMM, 1-pass fp16, 3-stage pipeline ----------------
// C[M,Nn] = A[M,K] @ Bw[Nn,K]^T + bias; fp32 or fp16 output (OUTH).
// K % 64 == 0, M % 128 == 0; Bw row-padded to gridDim.x*128. Nn even.
// Tile 128x128x64, SW128 smem, 3 stages x 32KB = 96KB. 2 CTAs/SM forced.
template <bool OUTH>
__global__ void __launch_bounds__(256, 2) gemm_f16(
    const __half* __restrict__ A, const __half* __restrict__ Bw,
    const float* __restrict__ bias,
    float* __restrict__ C, __half* __restrict__ Ch,
    int M, int Nn, int K)
{
    constexpr int TOFF_B = 16384;
    constexpr int TSTAGE = 32768;

    extern __shared__ char smem[];
    const uint32_t sbase = smem_u32(smem);
    const int tid = threadIdx.x;
    const int wid = tid >> 5, lid = tid & 31;
    const int m0 = blockIdx.y * 128;
    const int n0 = blockIdx.x * 128;

    const int wm = wid & 3;      // 0..3 -> 32-row slab
    const int wn = wid >> 2;     // 0..1 -> 64-col slab

    float acc[2][8][4];
#pragma unroll
    for (int i = 0; i < 2; i++)
#pragma unroll
        for (int j = 0; j < 8; j++)
#pragma unroll
            for (int q = 0; q < 4; q++) acc[i][j][q] = 0.f;

    const int lrow = tid >> 1;
    const int lkc0 = (tid & 1) * 4;

    const int nch = K / 64;

    auto load_stage = [&](int st, int c) {
        const int k0 = c * 64;
        const uint32_t stb = sbase + st * TSTAGE;
#pragma unroll
        for (int i = 0; i < 4; i++) {
            const int kc = lkc0 + i;
            const uint32_t so = SW128((uint32_t)(lrow * 128 + kc * 16));
            cp16(stb + so, A + (size_t)(m0 + lrow) * K + k0 + kc * 8);
            cp16(stb + TOFF_B + so, Bw + (size_t)(n0 + lrow) * K + k0 + kc * 8);
        }
        cp_commit();
    };

    load_stage(0, 0);
    if (nch > 1) load_stage(1, 1);

    const int lt = lid >> 3;   // ldmatrix tile index 0..3
    const int lr = lid & 7;    // row within tile

    int st = 0;
    for (int c = 0; c < nch; c++) {
        if (c + 2 < nch) {
            load_stage((st + 2) % 3, c + 2);
            asm volatile("cp.async.wait_group 2;");
        } else if (c + 1 < nch) {
            asm volatile("cp.async.wait_group 1;");
        } else {
            asm volatile("cp.async.wait_group 0;");
        }
        __syncthreads();

        const uint32_t stb = sbase + st * TSTAGE;
#pragma unroll
        for (int kk = 0; kk < 4; kk++) {
            const int kc = kk * 2 + (lt >> 1);
            uint32_t aH[2][4];
#pragma unroll
            for (int mt = 0; mt < 2; mt++) {
                const int row = wm * 32 + mt * 16 + (lt & 1) * 8 + lr;
                const uint32_t so = SW128((uint32_t)(row * 128 + kc * 16));
                ldm4(aH[mt][0], aH[mt][1], aH[mt][2], aH[mt][3], stb + so);
            }
            uint32_t bf[8][2];
#pragma unroll
            for (int nt = 0; nt < 4; nt++) {
                const int row = wn * 64 + nt * 16 + (lt & 1) * 8 + lr;
                const uint32_t so = SW128((uint32_t)(row * 128 + kc * 16));
                uint32_t q0, q1, q2, q3;
                ldm4(q0, q1, q2, q3, stb + TOFF_B + so);
                bf[nt * 2][0] = q0; bf[nt * 2][1] = q2;
                bf[nt * 2 + 1][0] = q1; bf[nt * 2 + 1][1] = q3;
            }
#pragma unroll
            for (int mt = 0; mt < 2; mt++)
#pragma unroll
                for (int ns = 0; ns < 8; ns++)
                    mma16816(acc[mt][ns], aH[mt], bf[ns]);
        }
        __syncthreads();
        st = (st + 1) % 3;
    }

    // epilogue (vectorized: col pairs are contiguous, Nn even, col always even)
    const int gq = lid >> 2;
    const int tq = lid & 3;
#pragma unroll
    for (int mt = 0; mt < 2; mt++) {
#pragma unroll
        for (int ns = 0; ns < 8; ns++) {
            const int col = n0 + wn * 64 + ns * 8 + tq * 2;
            const int r0 = m0 + wm * 32 + mt * 16 + gq;
            if (col < Nn) {
                const float b0 = bias[col], b1 = bias[col + 1];
                if (OUTH) {
                    __half2 v0 = __floats2half2_rn(acc[mt][ns][0] + b0, acc[mt][ns][1] + b1);
                    __half2 v1 = __floats2half2_rn(acc[mt][ns][2] + b0, acc[mt][ns][3] + b1);
                    *reinterpret_cast<__half2*>(Ch + (size_t)r0 * Nn + col)       = v0;
                    *reinterpret_cast<__half2*>(Ch + (size_t)(r0 + 8) * Nn + col) = v1;
                } else {
                    float2 v0 = make_float2(acc[mt][ns][0] + b0, acc[mt][ns][1] + b1);
                    float2 v1 = make_float2(acc[mt][ns][2] + b0, acc[mt][ns][3] + b1);
                    *reinterpret_cast<float2*>(C + (size_t)r0 * Nn + col)       = v0;
                    *reinterpret_cast<float2*>(C + (size_t)(r0 + 8) * Nn + col) = v1;
                }
            }
        }
    }
}

// ---------------- GRU pointwise gates ----------------
__global__ void __launch_bounds__(256) gru_gate(
    const float* __restrict__ gi_all, const float* __restrict__ gh,
    const float* __restrict__ gh_bias,
    float* __restrict__ h, __half* __restrict__ h16, __half* __restrict__ y16,
    int t)
{
    const int idx = blockIdx.x * blockDim.x + threadIdx.x;
    if (idx >= B_ * H_) return;
    const int b = idx / H_;
    const int j = idx % H_;

    const float* gi = gi_all + (size_t)(b * S_ + t) * G3H_;

    float hr, hz, hn, hprev;
    if (t == 0) {
        hr = gh_bias[j]; hz = gh_bias[H_ + j]; hn = gh_bias[2 * H_ + j];
        hprev = 0.f;
    } else {
        const float* ghb = gh + (size_t)b * G3H_;
        hr = ghb[j]; hz = ghb[H_ + j]; hn = ghb[2 * H_ + j];
        hprev = h[idx];
    }

    const float ir = gi[j], iz = gi[H_ + j], in = gi[2 * H_ + j];

    const float r = 1.f / (1.f + expf(-(ir + hr)));
    const float z = 1.f / (1.f + expf(-(iz + hz)));
    const float n = tanhf(in + r * hn);

    const float hnew = (1.f - z) * n + z * hprev;
    h[idx] = hnew;

    const __half hv = __float2half_rn(hnew);
    h16[(size_t)b * HPAD_ + j] = hv;
    y16[(size_t)b * YPAD_ + t * H_ + j] = hv;
}

// ---------------- launch ----------------
extern "C" void kernel_launch(void* const* d_in, const int* in_sizes, int n_in,
                              void* d_out, int out_size)
{
    const float* x          = (const float*)d_in[0];
    const int*   edge_index = (const int*)  d_in[1];
    const float* edge_f     = (const float*)d_in[2];
    const float* edge_attr  = (const float*)d_in[3];
    const float* Wx         = (const float*)d_in[4];
    const float* We         = (const float*)d_in[5];
    const float* Wf         = (const float*)d_in[6];
    const float* Wedge      = (const float*)d_in[7];
    const float* w_ih       = (const float*)d_in[8];
    const float* w_hh       = (const float*)d_in[9];
    const float* b_ih       = (const float*)d_in[10];
    const float* b_hh       = (const float*)d_in[11];
    const float* mlp_w1     = (const float*)d_in[12];
    const float* mlp_b1     = (const float*)d_in[13];
    const float* mlp_w2     = (const float*)d_in[14];
    const float* mlp_b2     = (const float*)d_in[15];
    float* out = (float*)d_out;

    __half *p_seq, *p_wih, *p_whh, *p_w1t, *p_w2t, *p_h16, *p_y16, *p_z1;
    float *p_gi, *p_gh, *p_h;
    cudaGetSymbolAddress((void**)&p_seq, g_seq16);
    cudaGetSymbolAddress((void**)&p_wih, g_wih16);
    cudaGetSymbolAddress((void**)&p_whh, g_whh16);
    cudaGetSymbolAddress((void**)&p_w1t, g_w1t16);
    cudaGetSymbolAddress((void**)&p_w2t, g_w2t16);
    cudaGetSymbolAddress((void**)&p_h16, g_h16);
    cudaGetSymbolAddress((void**)&p_y16, g_y16);
    cudaGetSymbolAddress((void**)&p_z1,  g_z1);
    cudaGetSymbolAddress((void**)&p_gi,  g_gi);
    cudaGetSymbolAddress((void**)&p_gh,  g_gh);
    cudaGetSymbolAddress((void**)&p_h,   g_h);

    cudaFuncSetAttribute(gemm_f16<false>, cudaFuncAttributeMaxDynamicSharedMemorySize, 3 * 32768);
    cudaFuncSetAttribute(gemm_f16<true>,  cudaFuncAttributeMaxDynamicSharedMemorySize, 3 * 32768);

    // 0) zero pads
    cudaMemsetAsync(p_h16, 0, sizeof(__half) * B_ * HPAD_);
    cudaMemsetAsync(p_y16, 0, sizeof(__half) * B_ * YPAD_);

    // 1) GNN -> seq fp16 ; fused weight conversion
    gnn_kernel<<<NG_, 256>>>(x, edge_index, edge_f, edge_attr, Wx, We, Wf, Wedge, p_seq);
    conv_all<<<NB_ALL, 256>>>(w_ih, w_hh, mlp_w1, mlp_w2, p_wih, p_whh, p_w1t, p_w2t);

    // 2) gi = seq @ w_ih^T + b_ih   [10240, 2400]
    {
        dim3 grid(G3HP_ / 128, NG_ / 128);   // 19 x 80
        gemm_f16<false><<<grid, 256, 3 * 32768>>>(p_seq, p_wih, b_ih,
                                                  p_gi, nullptr, NG_, G3H_, SEQ_);
    }

    // 3) GRU recurrence (t=0 skips the GEMM: gh == b_hh since h=0)
    {
        dim3 gridh(G3HP_ / 128, B_ / 128);   // 19 x 16
        for (int t = 0; t < S_; t++) {
            if (t > 0)
                gemm_f16<false><<<gridh, 256, 3 * 32768>>>(p_h16, p_whh, b_hh,
                                                           p_gh, nullptr, B_, G3H_, HPAD_);
            gru_gate<<<(B_ * H_ + 255) / 256, 256>>>(p_gi, p_gh, b_hh,
                                                     p_h, p_h16, p_y16, t);
        }
    }

    // 4) MLP
    {
        dim3 g1(MLP1_ / 128, B_ / 128);      // 10 x 16
        gemm_f16<true><<<g1, 256, 3 * 32768>>>(p_y16, p_w1t, mlp_b1,
                                               nullptr, p_z1, B_, MLP1_, YPAD_);
        dim3 g2(OUTNP_ / 128, B_ / 128);     // 4 x 16
        gemm_f16<false><<<g2, 256, 3 * 32768>>>(p_z1, p_w2t, mlp_b2,
                                                out, nullptr, B_, OUTN_, MLP1_);
    }
}